// round 14
// baseline (speedup 1.0000x reference)
#include <cuda_runtime.h>
#include <cuda_bf16.h>
#include <cstdint>

#define MAX_N 50000
#define MAX_E 800000
#define HDIM  64

// ---------------- scratch (no allocations allowed) ----------------
__device__ float g_tx [2L * MAX_N * HDIM];   // layer-1 per-relation messages
__device__ float g_tx2[2L * MAX_N * HDIM];   // layer-2 per-relation messages
__device__ float g_bufA[MAX_N * HDIM];       // layer-1 self-loop (+relu input)
__device__ float g_bufB[MAX_N * HDIM];       // layer-2 self-loop
__device__ float g_ev[2L * MAX_N * 2];
__device__ int   g_cnt[MAX_N];
__device__ int   g_off[MAX_N + 1];
__device__ int   g_pos[MAX_N];
__device__ int   g_bsum[64];
__device__ unsigned g_elist[MAX_E];
__device__ unsigned g_min_key;
__device__ __nv_bfloat16 g_w1h[3 * 128 * 64], g_w1l[3 * 128 * 64];
__device__ __nv_bfloat16 g_w2h[3 * 64 * 64],  g_w2l[3 * 64 * 64];

__device__ __forceinline__ unsigned fenc(float f) {
    unsigned b = __float_as_uint(f);
    return (b & 0x80000000u) ? ~b : (b | 0x80000000u);
}
__device__ __forceinline__ float fdec(unsigned k) {
    unsigned b = (k & 0x80000000u) ? (k ^ 0x80000000u) : ~k;
    return __uint_as_float(b);
}
__device__ __forceinline__ void split_bf16(float v, __nv_bfloat16& h, __nv_bfloat16& l) {
    h = __float2bfloat16(v);
    l = __float2bfloat16(v - __bfloat162float(h));
}

// ---------------- PDL primitives ----------------
__device__ __forceinline__ void pdl_trigger() {
    asm volatile("griddepcontrol.launch_dependents;");
}
__device__ __forceinline__ void pdl_wait() {
    asm volatile("griddepcontrol.wait;" ::: "memory");
}

// ================= setup A: presplit weights (main stream) =================
__global__ void setupA_kernel(const float* __restrict__ W1, const float* __restrict__ L1,
                              const float* __restrict__ W2, const float* __restrict__ L2)
{
    int i = blockIdx.x * blockDim.x + threadIdx.x;
    if (i < 24576) {
        float v = (i < 16384) ? W1[i] : L1[i - 16384];
        split_bf16(v, g_w1h[i], g_w1l[i]);
    } else if (i < 36864) {
        int j = i - 24576;
        float v = (j < 8192) ? W2[j] : L2[j - 8192];
        split_bf16(v, g_w2h[j], g_w2l[j]);
    }
}

// ================= setup B: zero counters + sentinels (CSR stream) =========
__global__ void setupB_kernel(int N)
{
    int i = blockIdx.x * blockDim.x + threadIdx.x;
    if (i < N) g_cnt[i] = 0;
    if (i < 64) g_bsum[i] = -1;
    if (i == 0) g_min_key = 0xFFFFFFFFu;
}

// ================= CSR build =================
__global__ void hist_kernel(const int* __restrict__ dst, int E) {
    int e = blockIdx.x * blockDim.x + threadIdx.x;
    if (e < E) atomicAdd(&g_cnt[dst[e]], 1);
}

__global__ void __launch_bounds__(1024) scan_kernel(int N, int E) {
    __shared__ int sa[1024], sb[1024];
    __shared__ int bpre;
    const int tid = threadIdx.x;
    const int i = blockIdx.x * 1024 + tid;
    int v = (i < N) ? g_cnt[i] : 0;
    sa[tid] = v;
    __syncthreads();
    int* in = sa; int* out = sb;
    #pragma unroll
    for (int o = 1; o < 1024; o <<= 1) {
        out[tid] = in[tid] + (tid >= o ? in[tid - o] : 0);
        __syncthreads();
        int* t = in; in = out; out = t;
    }
    if (tid == 1023)
        ((volatile int*)g_bsum)[blockIdx.x] = in[1023];
    if (tid < 32) {
        int run = 0;
        for (int base = 0; base < blockIdx.x; base += 32) {
            int idx = base + tid;
            int bv = 0;
            if (idx < blockIdx.x) {
                do { bv = ((volatile int*)g_bsum)[idx]; } while (bv < 0);
            }
            #pragma unroll
            for (int o = 16; o; o >>= 1) bv += __shfl_xor_sync(0xffffffffu, bv, o);
            run += bv;
        }
        if (tid == 0) bpre = run;
    }
    __syncthreads();
    if (i < N) {
        int o = bpre + in[tid] - v;
        g_off[i] = o;
        g_pos[i] = o;
    }
    if (i == 0) g_off[N] = E;
}

__global__ void fill_kernel(const int* __restrict__ src,
                            const int* __restrict__ dst,
                            const int* __restrict__ et, int E) {
    int e = blockIdx.x * blockDim.x + threadIdx.x;
    if (e >= E) return;
    int p = atomicAdd(&g_pos[dst[e]], 1);
    g_elist[p] = (unsigned)src[e] | ((unsigned)et[e] << 16);
}

// ================= tensor-core helpers =================
__device__ __forceinline__ void ldsm_x4(uint32_t* r, const void* p) {
    uint32_t a = (uint32_t)__cvta_generic_to_shared(p);
    asm volatile("ldmatrix.sync.aligned.m8n8.x4.shared.b16 {%0,%1,%2,%3}, [%4];"
        : "=r"(r[0]), "=r"(r[1]), "=r"(r[2]), "=r"(r[3]) : "r"(a));
}
__device__ __forceinline__ void ldsm_x2t(uint32_t* r, const void* p) {
    uint32_t a = (uint32_t)__cvta_generic_to_shared(p);
    asm volatile("ldmatrix.sync.aligned.m8n8.x2.trans.shared.b16 {%0,%1}, [%2];"
        : "=r"(r[0]), "=r"(r[1]) : "r"(a));
}
__device__ __forceinline__ void mma_bf16(float* c, const uint32_t* a, const uint32_t* b) {
    asm volatile("mma.sync.aligned.m16n8k16.row.col.f32.bf16.bf16.f32 "
        "{%0,%1,%2,%3}, {%4,%5,%6,%7}, {%8,%9}, {%0,%1,%2,%3};"
        : "+f"(c[0]), "+f"(c[1]), "+f"(c[2]), "+f"(c[3])
        : "r"(a[0]), "r"(a[1]), "r"(a[2]), "r"(a[3]), "r"(b[0]), "r"(b[1]));
}

// ================= layer-1 GEMM (R7-proven, K=128) =================
__global__ void __launch_bounds__(512, 1) gemm1_kernel(
    const float* __restrict__ A, int M,
    const __nv_bfloat16* __restrict__ Wh, const __nv_bfloat16* __restrict__ Wl,
    const float* __restrict__ bias,
    float* __restrict__ C0, float* __restrict__ C1, float* __restrict__ Cl)
{
    constexpr int K = 128, BM = 128, AS = K + 8, WS = 72;
    extern __shared__ __nv_bfloat16 sm[];
    __nv_bfloat16* Ahi = sm;
    __nv_bfloat16* Alo = Ahi + BM * AS;
    __nv_bfloat16* Whs = Alo + BM * AS;
    __nv_bfloat16* Wls = Whs + 3 * K * WS;

    const int tid  = threadIdx.x;
    const int lane = tid & 31;
    const int warp = tid >> 5;
    const int rowBase = blockIdx.x * BM;

    pdl_trigger();

    for (int u = tid; u < 3 * K * 8; u += 512) {
        int row = u >> 3, col = (u & 7) * 8;
        *(uint4*)&Whs[row * WS + col] = *(const uint4*)&Wh[row * 64 + col];
        *(uint4*)&Wls[row * WS + col] = *(const uint4*)&Wl[row * 64 + col];
    }
    for (int i = tid * 4; i < BM * K; i += 2048) {
        int r = i / K, kq = i % K;
        float4 v = make_float4(0.f, 0.f, 0.f, 0.f);
        if (rowBase + r < M) v = *(const float4*)&A[(long)(rowBase + r) * K + kq];
        float vv[4] = {v.x, v.y, v.z, v.w};
        #pragma unroll
        for (int j = 0; j < 4; j++) {
            __nv_bfloat16 h, l;
            split_bf16(vv[j], h, l);
            Ahi[r * AS + kq + j] = h;
            Alo[r * AS + kq + j] = l;
        }
    }
    __syncthreads();

    const int mw = (warp & 3) * 32;
    const int nw = (warp >> 2) * 48;
    const int lr = lane & 15;
    const int aCol = (lane >> 4) * 8;

    float acc[2][6][4];
    #pragma unroll
    for (int mt = 0; mt < 2; mt++)
        #pragma unroll
        for (int j = 0; j < 6; j++)
            #pragma unroll
            for (int q = 0; q < 4; q++) acc[mt][j][q] = 0.f;

    #pragma unroll
    for (int kk = 0; kk < K / 16; kk++) {
        uint32_t ah[2][4], al[2][4];
        #pragma unroll
        for (int mt = 0; mt < 2; mt++) {
            ldsm_x4(ah[mt], &Ahi[(mw + mt * 16 + lr) * AS + kk * 16 + aCol]);
            ldsm_x4(al[mt], &Alo[(mw + mt * 16 + lr) * AS + kk * 16 + aCol]);
        }
        #pragma unroll
        for (int j = 0; j < 6; j++) {
            int n = nw + j * 8;
            int w = n >> 6, nc = n & 63;
            long woff = (long)(w * K + kk * 16 + lr) * WS + nc;
            uint32_t bh[2], bl[2];
            ldsm_x2t(bh, &Whs[woff]);
            ldsm_x2t(bl, &Wls[woff]);
            mma_bf16(acc[0][j], ah[0], bh);
            mma_bf16(acc[0][j], ah[0], bl);
            mma_bf16(acc[0][j], al[0], bh);
            mma_bf16(acc[1][j], ah[1], bh);
            mma_bf16(acc[1][j], ah[1], bl);
            mma_bf16(acc[1][j], al[1], bh);
        }
    }

    float* Cs[3] = {C0, C1, Cl};
    #pragma unroll
    for (int mt = 0; mt < 2; mt++) {
        const int r0 = rowBase + mw + mt * 16 + (lane >> 2);
        #pragma unroll
        for (int j = 0; j < 6; j++) {
            int n = nw + j * 8;
            int w = n >> 6;
            int nc = (n & 63) + 2 * (lane & 3);
            float b0 = 0.f, b1 = 0.f;
            if (w == 2) { b0 = bias[nc]; b1 = bias[nc + 1]; }
            if (r0 < M)
                *(float2*)&Cs[w][(long)r0 * 64 + nc] =
                    make_float2(acc[mt][j][0] + b0, acc[mt][j][1] + b1);
            if (r0 + 8 < M)
                *(float2*)&Cs[w][(long)(r0 + 8) * 64 + nc] =
                    make_float2(acc[mt][j][2] + b0, acc[mt][j][3] + b1);
        }
    }
}

// ================= FUSED gather1 + layer-2 GEMM (K=64) =================
// Each CTA gathers its 128 nodes' layer-1 aggregation (R10-proven MLP-4 loop,
// one warp x 8 nodes), relu + bf16-splits straight into the A smem tiles,
// then runs the proven MMA. bufA round-trip and a kernel boundary vanish;
// gather stalls overlap with the weight prologue + MMA.
__global__ void __launch_bounds__(512, 1) gemm2_fused_kernel(
    const float* __restrict__ selfA,            // bufA: self-loop + bias
    const float* __restrict__ t, int M, int N,  // tx: layer-1 messages
    const __nv_bfloat16* __restrict__ Wh, const __nv_bfloat16* __restrict__ Wl,
    const float* __restrict__ bias,
    float* __restrict__ C0, float* __restrict__ C1, float* __restrict__ Cl)
{
    constexpr int K = 64, BM = 128, AS = K + 8, WS = 72;
    extern __shared__ __nv_bfloat16 sm[];
    __nv_bfloat16* Ahi = sm;
    __nv_bfloat16* Alo = Ahi + BM * AS;
    __nv_bfloat16* Whs = Alo + BM * AS;
    __nv_bfloat16* Wls = Whs + 3 * K * WS;

    const int tid  = threadIdx.x;
    const int lane = tid & 31;
    const int warp = tid >> 5;
    const int rowBase = blockIdx.x * BM;

    pdl_trigger();

    // weights: old data (setupA, 2 kernels back) -> pre-wait
    for (int u = tid; u < 3 * K * 8; u += 512) {
        int row = u >> 3, col = (u & 7) * 8;
        *(uint4*)&Whs[row * WS + col] = *(const uint4*)&Wh[row * 64 + col];
        *(uint4*)&Wls[row * WS + col] = *(const uint4*)&Wl[row * 64 + col];
    }

    pdl_wait();   // selfA / t written by gemm1 (immediate predecessor)

    // ---- gather + relu + split: each warp handles 8 consecutive rows ----
    const int lq = lane * 2;
    #pragma unroll 1
    for (int i = 0; i < 8; i++) {
        int r = warp * 8 + i;
        int w = rowBase + r;
        float x0 = 0.f, x1 = 0.f;
        if (w < M) {
            int beg = g_off[w], end = g_off[w + 1];
            long o = (long)w * 64 + lq;
            float2 a0 = *(const float2*)&selfA[o];
            float2 a1 = make_float2(0.f, 0.f), a2 = a1, a3 = a1;
            int e = beg;
            for (; e + 4 <= end; e += 4) {
                unsigned p0 = g_elist[e],     p1 = g_elist[e + 1];
                unsigned p2 = g_elist[e + 2], p3 = g_elist[e + 3];
                float2 v0 = *(const float2*)&t[(long)((p0 >> 16) * N + (p0 & 0xFFFFu)) * 64 + lq];
                float2 v1 = *(const float2*)&t[(long)((p1 >> 16) * N + (p1 & 0xFFFFu)) * 64 + lq];
                float2 v2 = *(const float2*)&t[(long)((p2 >> 16) * N + (p2 & 0xFFFFu)) * 64 + lq];
                float2 v3 = *(const float2*)&t[(long)((p3 >> 16) * N + (p3 & 0xFFFFu)) * 64 + lq];
                a0.x += v0.x; a0.y += v0.y;
                a1.x += v1.x; a1.y += v1.y;
                a2.x += v2.x; a2.y += v2.y;
                a3.x += v3.x; a3.y += v3.y;
            }
            for (; e < end; e++) {
                unsigned p = g_elist[e];
                float2 v = *(const float2*)&t[(long)((p >> 16) * N + (p & 0xFFFFu)) * 64 + lq];
                a0.x += v.x; a0.y += v.y;
            }
            x0 = fmaxf(a0.x + a1.x + a2.x + a3.x, 0.f);
            x1 = fmaxf(a0.y + a1.y + a2.y + a3.y, 0.f);
        }
        __nv_bfloat16 h0, l0, h1, l1;
        split_bf16(x0, h0, l0);
        split_bf16(x1, h1, l1);
        *(__nv_bfloat162*)&Ahi[r * AS + lq] = __nv_bfloat162(h0, h1);
        *(__nv_bfloat162*)&Alo[r * AS + lq] = __nv_bfloat162(l0, l1);
    }
    __syncthreads();

    // ---- MMA (identical to proven K=64 path) ----
    const int mw = (warp & 3) * 32;
    const int nw = (warp >> 2) * 48;
    const int lr = lane & 15;
    const int aCol = (lane >> 4) * 8;

    float acc[2][6][4];
    #pragma unroll
    for (int mt = 0; mt < 2; mt++)
        #pragma unroll
        for (int j = 0; j < 6; j++)
            #pragma unroll
            for (int q = 0; q < 4; q++) acc[mt][j][q] = 0.f;

    #pragma unroll
    for (int kk = 0; kk < K / 16; kk++) {
        uint32_t ah[2][4], al[2][4];
        #pragma unroll
        for (int mt = 0; mt < 2; mt++) {
            ldsm_x4(ah[mt], &Ahi[(mw + mt * 16 + lr) * AS + kk * 16 + aCol]);
            ldsm_x4(al[mt], &Alo[(mw + mt * 16 + lr) * AS + kk * 16 + aCol]);
        }
        #pragma unroll
        for (int j = 0; j < 6; j++) {
            int n = nw + j * 8;
            int w = n >> 6, nc = n & 63;
            long woff = (long)(w * K + kk * 16 + lr) * WS + nc;
            uint32_t bh[2], bl[2];
            ldsm_x2t(bh, &Whs[woff]);
            ldsm_x2t(bl, &Wls[woff]);
            mma_bf16(acc[0][j], ah[0], bh);
            mma_bf16(acc[0][j], ah[0], bl);
            mma_bf16(acc[0][j], al[0], bh);
            mma_bf16(acc[1][j], ah[1], bh);
            mma_bf16(acc[1][j], ah[1], bl);
            mma_bf16(acc[1][j], al[1], bh);
        }
    }

    float* Cs[3] = {C0, C1, Cl};
    #pragma unroll
    for (int mt = 0; mt < 2; mt++) {
        const int r0 = rowBase + mw + mt * 16 + (lane >> 2);
        #pragma unroll
        for (int j = 0; j < 6; j++) {
            int n = nw + j * 8;
            int w = n >> 6;
            int nc = (n & 63) + 2 * (lane & 3);
            float b0 = 0.f, b1 = 0.f;
            if (w == 2) { b0 = bias[nc]; b1 = bias[nc + 1]; }
            if (r0 < M)
                *(float2*)&Cs[w][(long)r0 * 64 + nc] =
                    make_float2(acc[mt][j][0] + b0, acc[mt][j][1] + b1);
            if (r0 + 8 < M)
                *(float2*)&Cs[w][(long)(r0 + 8) * 64 + nc] =
                    make_float2(acc[mt][j][2] + b0, acc[mt][j][3] + b1);
        }
    }
}

// ================= gather2 + fused layer-3 (R10-proven) + PDL ===============
__global__ void gather_final_kernel(const float* __restrict__ t,
                                    float* __restrict__ agg, int N,
                                    const float* __restrict__ W3,
                                    const float* __restrict__ L3,
                                    const float* __restrict__ b3,
                                    float* __restrict__ ev,
                                    float* __restrict__ out)
{
    pdl_trigger();

    __shared__ float sW0[128], sW1[128], sL[128], sb[2];
    {
        int tid = threadIdx.x;
        for (int i = tid; i < 128; i += blockDim.x) {
            sW0[i] = W3[i];
            sW1[i] = W3[128 + i];
            sL[i]  = L3[i];
        }
        if (tid < 2) sb[tid] = b3[tid];
        __syncthreads();
    }

    int w = (int)((blockIdx.x * (long)blockDim.x + threadIdx.x) >> 5);
    int lane = threadIdx.x & 31;
    if (w >= N) return;
    int beg = g_off[w], end = g_off[w + 1];

    pdl_wait();   // agg / t written by immediate predecessor

    long o = (long)w * 64 + lane * 2;
    float2 a0 = *(float2*)&agg[o];
    float2 a1 = make_float2(0.f, 0.f), a2 = a1, a3 = a1;
    int e = beg;
    for (; e + 4 <= end; e += 4) {
        unsigned p0 = g_elist[e],     p1 = g_elist[e + 1];
        unsigned p2 = g_elist[e + 2], p3 = g_elist[e + 3];
        float2 v0 = *(const float2*)&t[(long)((p0 >> 16) * N + (p0 & 0xFFFFu)) * 64 + lane * 2];
        float2 v1 = *(const float2*)&t[(long)((p1 >> 16) * N + (p1 & 0xFFFFu)) * 64 + lane * 2];
        float2 v2 = *(const float2*)&t[(long)((p2 >> 16) * N + (p2 & 0xFFFFu)) * 64 + lane * 2];
        float2 v3 = *(const float2*)&t[(long)((p3 >> 16) * N + (p3 & 0xFFFFu)) * 64 + lane * 2];
        a0.x += v0.x; a0.y += v0.y;
        a1.x += v1.x; a1.y += v1.y;
        a2.x += v2.x; a2.y += v2.y;
        a3.x += v3.x; a3.y += v3.y;
    }
    for (; e < end; e++) {
        unsigned p = g_elist[e];
        float2 v = *(const float2*)&t[(long)((p >> 16) * N + (p & 0xFFFFu)) * 64 + lane * 2];
        a0.x += v.x; a0.y += v.y;
    }
    a0.x += a1.x + a2.x + a3.x;
    a0.y += a1.y + a2.y + a3.y;

    float x0 = fmaxf(a0.x, 0.f), x1 = fmaxf(a0.y, 0.f);
    int k0 = lane * 2, k1 = lane * 2 + 1;
    float p0 = x0 * sW0[k0 * 2 + 0] + x1 * sW0[k1 * 2 + 0];
    float p1 = x0 * sW0[k0 * 2 + 1] + x1 * sW0[k1 * 2 + 1];
    float p2 = x0 * sW1[k0 * 2 + 0] + x1 * sW1[k1 * 2 + 0];
    float p3 = x0 * sW1[k0 * 2 + 1] + x1 * sW1[k1 * 2 + 1];
    float p4 = x0 * sL[k0 * 2 + 0]  + x1 * sL[k1 * 2 + 0];
    float p5 = x0 * sL[k0 * 2 + 1]  + x1 * sL[k1 * 2 + 1];
    #pragma unroll
    for (int off = 16; off; off >>= 1) {
        p0 += __shfl_xor_sync(0xffffffffu, p0, off);
        p1 += __shfl_xor_sync(0xffffffffu, p1, off);
        p2 += __shfl_xor_sync(0xffffffffu, p2, off);
        p3 += __shfl_xor_sync(0xffffffffu, p3, off);
        p4 += __shfl_xor_sync(0xffffffffu, p4, off);
        p5 += __shfl_xor_sync(0xffffffffu, p5, off);
    }
    if (lane == 0) {
        *(float2*)&ev[(long)w * 2]       = make_float2(p0, p1);
        *(float2*)&ev[((long)N + w) * 2] = make_float2(p2, p3);
        *(float2*)&out[(long)w * 2]      = make_float2(p4 + sb[0], p5 + sb[1]);
    }
}

// ================= ev-gather + global min (R10-proven) + PDL ================
__global__ void gatherev_min_kernel(const float* __restrict__ ev,
                                    float* __restrict__ out, int N)
{
    pdl_trigger();
    int n = blockIdx.x * blockDim.x + threadIdx.x;
    int beg = 0, end = 0;
    if (n < N) { beg = g_off[n]; end = g_off[n + 1]; }
    pdl_wait();

    float m = 3.402823466e+38f;
    if (n < N) {
        float2 a0 = *(float2*)&out[n * 2];
        float2 a1 = make_float2(0.f, 0.f), a2 = a1, a3 = a1;
        int e = beg;
        for (; e + 4 <= end; e += 4) {
            unsigned p0 = g_elist[e],     p1 = g_elist[e + 1];
            unsigned p2 = g_elist[e + 2], p3 = g_elist[e + 3];
            float2 v0 = *(const float2*)&ev[(long)((p0 >> 16) * N + (p0 & 0xFFFFu)) * 2];
            float2 v1 = *(const float2*)&ev[(long)((p1 >> 16) * N + (p1 & 0xFFFFu)) * 2];
            float2 v2 = *(const float2*)&ev[(long)((p2 >> 16) * N + (p2 & 0xFFFFu)) * 2];
            float2 v3 = *(const float2*)&ev[(long)((p3 >> 16) * N + (p3 & 0xFFFFu)) * 2];
            a0.x += v0.x; a0.y += v0.y;
            a1.x += v1.x; a1.y += v1.y;
            a2.x += v2.x; a2.y += v2.y;
            a3.x += v3.x; a3.y += v3.y;
        }
        for (; e < end; e++) {
            unsigned p = g_elist[e];
            float2 v = *(const float2*)&ev[(long)((p >> 16) * N + (p & 0xFFFFu)) * 2];
            a0.x += v.x; a0.y += v.y;
        }
        a0.x += a1.x + a2.x + a3.x;
        a0.y += a1.y + a2.y + a3.y;
        *(float2*)&out[n * 2] = a0;
        m = fminf(a0.x, a0.y);
    }
    #pragma unroll
    for (int o = 16; o; o >>= 1)
        m = fminf(m, __shfl_xor_sync(0xffffffffu, m, o));
    __shared__ float sm[8];
    if ((threadIdx.x & 31) == 0) sm[threadIdx.x >> 5] = m;
    __syncthreads();
    if (threadIdx.x < 8) {
        m = sm[threadIdx.x];
        #pragma unroll
        for (int o = 4; o; o >>= 1)
            m = fminf(m, __shfl_xor_sync(0xffu, m, o));
        if (threadIdx.x == 0) atomicMin(&g_min_key, fenc(m));
    }
}

__global__ void mask_kernel(float* __restrict__ out,
                            const int* __restrict__ cs,
                            const int* __restrict__ ms, int N)
{
    pdl_wait();
    int n = blockIdx.x * blockDim.x + threadIdx.x;
    if (n >= N) return;
    float mn = fdec(g_min_key) - 1.0f;
    float2 v = *(float2*)&out[n * 2];
    if (cs[n] >= ms[n] - 1) v.x = mn;
    if (cs[n] == 0)         v.y = mn;
    *(float2*)&out[n * 2] = v;
}

// ================= launch =================
extern "C" void kernel_launch(void* const* d_in, const int* in_sizes, int n_in,
                              void* d_out, int out_size)
{
    const float* x  = (const float*)d_in[0];
    const int* src  = (const int*)d_in[1];
    const int* dst  = (const int*)d_in[2];
    const int* et   = (const int*)d_in[3];
    const int* cs   = (const int*)d_in[4];
    const int* ms   = (const int*)d_in[5];
    const float* W1 = (const float*)d_in[6];
    const float* L1 = (const float*)d_in[7];
    const float* b1 = (const float*)d_in[8];
    const float* W2 = (const float*)d_in[9];
    const float* L2 = (const float*)d_in[10];
    const float* b2 = (const float*)d_in[11];
    const float* W3 = (const float*)d_in[12];
    const float* L3 = (const float*)d_in[13];
    const float* b3 = (const float*)d_in[14];

    const int N = in_sizes[0] / 128;
    const int E = in_sizes[1];
    float* out = (float*)d_out;

    float *tx, *tx2, *bufA, *bufB, *ev;
    __nv_bfloat16 *w1h, *w1l, *w2h, *w2l;
    cudaGetSymbolAddress((void**)&tx,   g_tx);
    cudaGetSymbolAddress((void**)&tx2,  g_tx2);
    cudaGetSymbolAddress((void**)&bufA, g_bufA);
    cudaGetSymbolAddress((void**)&bufB, g_bufB);
    cudaGetSymbolAddress((void**)&ev,   g_ev);
    cudaGetSymbolAddress((void**)&w1h,  g_w1h);
    cudaGetSymbolAddress((void**)&w1l,  g_w1l);
    cudaGetSymbolAddress((void**)&w2h,  g_w2h);
    cudaGetSymbolAddress((void**)&w2l,  g_w2l);

    constexpr int SMEM1 = (2 * 128 * (128 + 8) + 2 * 3 * 128 * 72) * 2;  // 180224
    constexpr int SMEM2 = (2 * 128 * (64 + 8)  + 2 * 3 * 64  * 72) * 2;  // 92160
    cudaFuncSetAttribute(gemm1_kernel,
                         cudaFuncAttributeMaxDynamicSharedMemorySize, SMEM1);
    cudaFuncSetAttribute(gemm2_fused_kernel,
                         cudaFuncAttributeMaxDynamicSharedMemorySize, SMEM2);

    static cudaStream_t s2 = nullptr;
    static cudaEvent_t evFork = nullptr, evCSR = nullptr;
    if (!s2) {
        cudaStreamCreateWithFlags(&s2, cudaStreamNonBlocking);
        cudaEventCreateWithFlags(&evFork, cudaEventDisableTiming);
        cudaEventCreateWithFlags(&evCSR,  cudaEventDisableTiming);
    }

    const int numTiles = (N + 127) / 128;
    int nodeBlocks = (N + 255) / 256;
    int edgeBlocks = (E + 255) / 256;
    int gatherBlocks = (N * 32 + 255) / 256;
    int scanBlocks = (N + 1023) / 1024;

    cudaLaunchAttribute pdlAttr;
    pdlAttr.id = cudaLaunchAttributeProgrammaticStreamSerialization;
    pdlAttr.val.programmaticStreamSerializationAllowed = 1;
    auto mkcfg = [&](int g, int b, size_t smem) {
        cudaLaunchConfig_t c{};
        c.gridDim = dim3(g); c.blockDim = dim3(b);
        c.dynamicSmemBytes = smem; c.stream = 0;
        c.attrs = &pdlAttr; c.numAttrs = 1;
        return c;
    };

    // fork CSR branch immediately
    cudaEventRecord(evFork, 0);
    cudaStreamWaitEvent(s2, evFork, 0);

    // --- branch A (s2): CSR build ---
    setupB_kernel<<<nodeBlocks, 256, 0, s2>>>(N);
    hist_kernel<<<edgeBlocks, 256, 0, s2>>>(dst, E);
    scan_kernel<<<scanBlocks, 1024, 0, s2>>>(N, E);
    fill_kernel<<<edgeBlocks, 256, 0, s2>>>(src, dst, et, E);
    cudaEventRecord(evCSR, s2);

    // --- branch B (main): presplit + layer-1 GEMM ---
    setupA_kernel<<<(36864 + 255) / 256, 256>>>(W1, L1, W2, L2);
    gemm1_kernel<<<numTiles, 512, SMEM1>>>(x, N,
        w1h, w1l, b1, tx, tx + (long)N * 64, bufA);

    // --- join + PDL chain ---
    cudaStreamWaitEvent(0, evCSR, 0);
    {
        // fused gather1 + gemm2: reads tx/bufA (pred) + CSR (event-gated)
        cudaLaunchConfig_t c = mkcfg(numTiles, 512, SMEM2);
        cudaLaunchKernelEx(&c, gemm2_fused_kernel,
            (const float*)bufA, (const float*)tx, N, N,
            (const __nv_bfloat16*)w2h, (const __nv_bfloat16*)w2l, b2,
            tx2, tx2 + (long)N * 64, bufB);
    }
    {
        cudaLaunchConfig_t c = mkcfg(gatherBlocks, 256, 0);
        cudaLaunchKernelEx(&c, gather_final_kernel,
            (const float*)tx2, bufB, N, W3, L3, b3, ev, out);
    }
    {
        cudaLaunchConfig_t c = mkcfg(nodeBlocks, 256, 0);
        cudaLaunchKernelEx(&c, gatherev_min_kernel, (const float*)ev, out, N);
    }
    {
        cudaLaunchConfig_t c = mkcfg(nodeBlocks, 256, 0);
        cudaLaunchKernelEx(&c, mask_kernel, out, cs, ms, N);
    }
}

// round 15
// speedup vs baseline: 1.2308x; 1.2308x over previous
#include <cuda_runtime.h>
#include <cuda_bf16.h>
#include <cstdint>

#define MAX_N 50000
#define MAX_E 800000
#define HDIM  64

// ---------------- scratch (no allocations allowed) ----------------
__device__ float g_tx[2L * MAX_N * HDIM];
__device__ float g_bufA[MAX_N * HDIM];
__device__ float g_bufB[MAX_N * HDIM];
__device__ float g_ev[2L * MAX_N * 2];
__device__ int   g_cnt[MAX_N];
__device__ int   g_off[MAX_N + 1];
__device__ int   g_rank[MAX_E];      // edge's rank within its dst list (from hist)
__device__ int   g_bsum[64];
__device__ unsigned g_elist[MAX_E];
__device__ unsigned g_min_key;
__device__ __nv_bfloat16 g_w1h[3 * 128 * 64], g_w1l[3 * 128 * 64];
__device__ __nv_bfloat16 g_w2h[3 * 64 * 64],  g_w2l[3 * 64 * 64];

__device__ __forceinline__ unsigned fenc(float f) {
    unsigned b = __float_as_uint(f);
    return (b & 0x80000000u) ? ~b : (b | 0x80000000u);
}
__device__ __forceinline__ float fdec(unsigned k) {
    unsigned b = (k & 0x80000000u) ? (k ^ 0x80000000u) : ~k;
    return __uint_as_float(b);
}
__device__ __forceinline__ void split_bf16(float v, __nv_bfloat16& h, __nv_bfloat16& l) {
    h = __float2bfloat16(v);
    l = __float2bfloat16(v - __bfloat162float(h));
}

// ---------------- PDL primitives ----------------
__device__ __forceinline__ void pdl_trigger() {
    asm volatile("griddepcontrol.launch_dependents;");
}
__device__ __forceinline__ void pdl_wait() {
    asm volatile("griddepcontrol.wait;" ::: "memory");
}

// ================= setup A: presplit weights (main stream) =================
__global__ void setupA_kernel(const float* __restrict__ W1, const float* __restrict__ L1,
                              const float* __restrict__ W2, const float* __restrict__ L2)
{
    int i = blockIdx.x * blockDim.x + threadIdx.x;
    if (i < 24576) {
        float v = (i < 16384) ? W1[i] : L1[i - 16384];
        split_bf16(v, g_w1h[i], g_w1l[i]);
    } else if (i < 36864) {
        int j = i - 24576;
        float v = (j < 8192) ? W2[j] : L2[j - 8192];
        split_bf16(v, g_w2h[j], g_w2l[j]);
    }
}

// ================= setup B: zero counters + sentinels (CSR stream) =========
__global__ void setupB_kernel(int N)
{
    int i = blockIdx.x * blockDim.x + threadIdx.x;
    if (i < N) g_cnt[i] = 0;
    if (i < 64) g_bsum[i] = -1;
    if (i == 0) g_min_key = 0xFFFFFFFFu;
}

// ================= CSR build =================
// hist's atomicAdd return value IS the edge's rank within its dst list —
// store it so fill needs no atomics at all.
__global__ void hist_kernel(const int* __restrict__ dst, int E) {
    int e = blockIdx.x * blockDim.x + threadIdx.x;
    if (e < E) g_rank[e] = atomicAdd(&g_cnt[dst[e]], 1);
}

__global__ void __launch_bounds__(1024) scan_kernel(int N, int E) {
    __shared__ int sa[1024], sb[1024];
    __shared__ int bpre;
    const int tid = threadIdx.x;
    const int i = blockIdx.x * 1024 + tid;
    int v = (i < N) ? g_cnt[i] : 0;
    sa[tid] = v;
    __syncthreads();
    int* in = sa; int* out = sb;
    #pragma unroll
    for (int o = 1; o < 1024; o <<= 1) {
        out[tid] = in[tid] + (tid >= o ? in[tid - o] : 0);
        __syncthreads();
        int* t = in; in = out; out = t;
    }
    if (tid == 1023)
        ((volatile int*)g_bsum)[blockIdx.x] = in[1023];
    if (tid < 32) {
        int run = 0;
        for (int base = 0; base < blockIdx.x; base += 32) {
            int idx = base + tid;
            int bv = 0;
            if (idx < blockIdx.x) {
                do { bv = ((volatile int*)g_bsum)[idx]; } while (bv < 0);
            }
            #pragma unroll
            for (int o = 16; o; o >>= 1) bv += __shfl_xor_sync(0xffffffffu, bv, o);
            run += bv;
        }
        if (tid == 0) bpre = run;
    }
    __syncthreads();
    if (i < N) g_off[i] = bpre + in[tid] - v;
    if (i == 0) g_off[N] = E;
}

// fill: atomic-free — coalesced reads + one scattered 4B store per edge
__global__ void fill_kernel(const int* __restrict__ src,
                            const int* __restrict__ dst,
                            const int* __restrict__ et, int E) {
    int e = blockIdx.x * blockDim.x + threadIdx.x;
    if (e >= E) return;
    int p = g_off[dst[e]] + g_rank[e];
    g_elist[p] = (unsigned)src[e] | ((unsigned)et[e] << 16);
}

// ================= tensor-core helpers =================
__device__ __forceinline__ void ldsm_x4(uint32_t* r, const void* p) {
    uint32_t a = (uint32_t)__cvta_generic_to_shared(p);
    asm volatile("ldmatrix.sync.aligned.m8n8.x4.shared.b16 {%0,%1,%2,%3}, [%4];"
        : "=r"(r[0]), "=r"(r[1]), "=r"(r[2]), "=r"(r[3]) : "r"(a));
}
__device__ __forceinline__ void ldsm_x2t(uint32_t* r, const void* p) {
    uint32_t a = (uint32_t)__cvta_generic_to_shared(p);
    asm volatile("ldmatrix.sync.aligned.m8n8.x2.trans.shared.b16 {%0,%1}, [%2];"
        : "=r"(r[0]), "=r"(r[1]) : "r"(a));
}
__device__ __forceinline__ void mma_bf16(float* c, const uint32_t* a, const uint32_t* b) {
    asm volatile("mma.sync.aligned.m16n8k16.row.col.f32.bf16.bf16.f32 "
        "{%0,%1,%2,%3}, {%4,%5,%6,%7}, {%8,%9}, {%0,%1,%2,%3};"
        : "+f"(c[0]), "+f"(c[1]), "+f"(c[2]), "+f"(c[3])
        : "r"(a[0]), "r"(a[1]), "r"(a[2]), "r"(a[3]), "r"(b[0]), "r"(b[1]));
}

// ================= tensor-core triple GEMM (R7-proven) + PDL ==============
template<int K, bool RELU_IN>
__global__ void __launch_bounds__(512, 1) gemm_tc2_kernel(
    const float* __restrict__ A, int M,
    const __nv_bfloat16* __restrict__ Wh, const __nv_bfloat16* __restrict__ Wl,
    const float* __restrict__ bias,
    float* __restrict__ C0, float* __restrict__ C1, float* __restrict__ Cl)
{
    constexpr int BM = 128;
    constexpr int AS = K + 8;
    constexpr int WS = 72;
    extern __shared__ __nv_bfloat16 sm[];
    __nv_bfloat16* Ahi = sm;
    __nv_bfloat16* Alo = Ahi + BM * AS;
    __nv_bfloat16* Whs = Alo + BM * AS;
    __nv_bfloat16* Wls = Whs + 3 * K * WS;

    const int tid  = threadIdx.x;
    const int lane = tid & 31;
    const int warp = tid >> 5;
    const int rowBase = blockIdx.x * BM;

    pdl_trigger();

    for (int u = tid; u < 3 * K * 8; u += 512) {
        int row = u >> 3, col = (u & 7) * 8;
        *(uint4*)&Whs[row * WS + col] = *(const uint4*)&Wh[row * 64 + col];
        *(uint4*)&Wls[row * WS + col] = *(const uint4*)&Wl[row * 64 + col];
    }

    if (K == 64) pdl_wait();   // gemm2: A comes from gather1 (immediate pred)

    for (int i = tid * 4; i < BM * K; i += 2048) {
        int r = i / K, kq = i % K;
        float4 v = make_float4(0.f, 0.f, 0.f, 0.f);
        if (rowBase + r < M) v = *(const float4*)&A[(long)(rowBase + r) * K + kq];
        float vv[4] = {v.x, v.y, v.z, v.w};
        #pragma unroll
        for (int j = 0; j < 4; j++) {
            float x = RELU_IN ? fmaxf(vv[j], 0.f) : vv[j];
            __nv_bfloat16 h, l;
            split_bf16(x, h, l);
            Ahi[r * AS + kq + j] = h;
            Alo[r * AS + kq + j] = l;
        }
    }
    __syncthreads();

    const int mw = (warp & 3) * 32;
    const int nw = (warp >> 2) * 48;
    const int lr = lane & 15;
    const int aCol = (lane >> 4) * 8;

    float acc[2][6][4];
    #pragma unroll
    for (int mt = 0; mt < 2; mt++)
        #pragma unroll
        for (int j = 0; j < 6; j++)
            #pragma unroll
            for (int q = 0; q < 4; q++) acc[mt][j][q] = 0.f;

    #pragma unroll
    for (int kk = 0; kk < K / 16; kk++) {
        uint32_t ah[2][4], al[2][4];
        #pragma unroll
        for (int mt = 0; mt < 2; mt++) {
            ldsm_x4(ah[mt], &Ahi[(mw + mt * 16 + lr) * AS + kk * 16 + aCol]);
            ldsm_x4(al[mt], &Alo[(mw + mt * 16 + lr) * AS + kk * 16 + aCol]);
        }
        #pragma unroll
        for (int j = 0; j < 6; j++) {
            int n = nw + j * 8;
            int w = n >> 6, nc = n & 63;
            long woff = (long)(w * K + kk * 16 + lr) * WS + nc;
            uint32_t bh[2], bl[2];
            ldsm_x2t(bh, &Whs[woff]);
            ldsm_x2t(bl, &Wls[woff]);
            mma_bf16(acc[0][j], ah[0], bh);
            mma_bf16(acc[0][j], ah[0], bl);
            mma_bf16(acc[0][j], al[0], bh);
            mma_bf16(acc[1][j], ah[1], bh);
            mma_bf16(acc[1][j], ah[1], bl);
            mma_bf16(acc[1][j], al[1], bh);
        }
    }

    float* Cs[3] = {C0, C1, Cl};
    #pragma unroll
    for (int mt = 0; mt < 2; mt++) {
        const int r0 = rowBase + mw + mt * 16 + (lane >> 2);
        #pragma unroll
        for (int j = 0; j < 6; j++) {
            int n = nw + j * 8;
            int w = n >> 6;
            int nc = (n & 63) + 2 * (lane & 3);
            float b0 = 0.f, b1 = 0.f;
            if (w == 2) { b0 = bias[nc]; b1 = bias[nc + 1]; }
            if (r0 < M)
                *(float2*)&Cs[w][(long)r0 * 64 + nc] =
                    make_float2(acc[mt][j][0] + b0, acc[mt][j][1] + b1);
            if (r0 + 8 < M)
                *(float2*)&Cs[w][(long)(r0 + 8) * 64 + nc] =
                    make_float2(acc[mt][j][2] + b0, acc[mt][j][3] + b1);
        }
    }
}

// ================= gather64 (R10-champion, MLP=4) + PDL ========================
template<bool FINAL>
__global__ void gather64_kernel(const float* __restrict__ t,
                                float* __restrict__ agg, int N,
                                const float* __restrict__ W3,
                                const float* __restrict__ L3,
                                const float* __restrict__ b3,
                                float* __restrict__ ev,
                                float* __restrict__ out)
{
    pdl_trigger();

    __shared__ float sW0[128], sW1[128], sL[128], sb[2];
    if (FINAL) {
        int tid = threadIdx.x;
        for (int i = tid; i < 128; i += blockDim.x) {
            sW0[i] = W3[i];
            sW1[i] = W3[128 + i];
            sL[i]  = L3[i];
        }
        if (tid < 2) sb[tid] = b3[tid];
        __syncthreads();
    }

    int w = (int)((blockIdx.x * (long)blockDim.x + threadIdx.x) >> 5);
    int lane = threadIdx.x & 31;
    if (w >= N) return;
    int beg = g_off[w], end = g_off[w + 1];

    pdl_wait();   // agg / t written by immediate predecessor

    long o = (long)w * 64 + lane * 2;
    float2 a0 = *(float2*)&agg[o];
    float2 a1 = make_float2(0.f, 0.f), a2 = a1, a3 = a1;
    int e = beg;
    for (; e + 4 <= end; e += 4) {
        unsigned p0 = g_elist[e],     p1 = g_elist[e + 1];
        unsigned p2 = g_elist[e + 2], p3 = g_elist[e + 3];
        float2 v0 = *(const float2*)&t[(long)((p0 >> 16) * N + (p0 & 0xFFFFu)) * 64 + lane * 2];
        float2 v1 = *(const float2*)&t[(long)((p1 >> 16) * N + (p1 & 0xFFFFu)) * 64 + lane * 2];
        float2 v2 = *(const float2*)&t[(long)((p2 >> 16) * N + (p2 & 0xFFFFu)) * 64 + lane * 2];
        float2 v3 = *(const float2*)&t[(long)((p3 >> 16) * N + (p3 & 0xFFFFu)) * 64 + lane * 2];
        a0.x += v0.x; a0.y += v0.y;
        a1.x += v1.x; a1.y += v1.y;
        a2.x += v2.x; a2.y += v2.y;
        a3.x += v3.x; a3.y += v3.y;
    }
    for (; e < end; e++) {
        unsigned p = g_elist[e];
        float2 v = *(const float2*)&t[(long)((p >> 16) * N + (p & 0xFFFFu)) * 64 + lane * 2];
        a0.x += v.x; a0.y += v.y;
    }
    a0.x += a1.x + a2.x + a3.x;
    a0.y += a1.y + a2.y + a3.y;

    if (!FINAL) {
        *(float2*)&agg[o] = a0;
        return;
    }

    float x0 = fmaxf(a0.x, 0.f), x1 = fmaxf(a0.y, 0.f);
    int k0 = lane * 2, k1 = lane * 2 + 1;
    float p0 = x0 * sW0[k0 * 2 + 0] + x1 * sW0[k1 * 2 + 0];
    float p1 = x0 * sW0[k0 * 2 + 1] + x1 * sW0[k1 * 2 + 1];
    float p2 = x0 * sW1[k0 * 2 + 0] + x1 * sW1[k1 * 2 + 0];
    float p3 = x0 * sW1[k0 * 2 + 1] + x1 * sW1[k1 * 2 + 1];
    float p4 = x0 * sL[k0 * 2 + 0]  + x1 * sL[k1 * 2 + 0];
    float p5 = x0 * sL[k0 * 2 + 1]  + x1 * sL[k1 * 2 + 1];
    #pragma unroll
    for (int off = 16; off; off >>= 1) {
        p0 += __shfl_xor_sync(0xffffffffu, p0, off);
        p1 += __shfl_xor_sync(0xffffffffu, p1, off);
        p2 += __shfl_xor_sync(0xffffffffu, p2, off);
        p3 += __shfl_xor_sync(0xffffffffu, p3, off);
        p4 += __shfl_xor_sync(0xffffffffu, p4, off);
        p5 += __shfl_xor_sync(0xffffffffu, p5, off);
    }
    if (lane == 0) {
        *(float2*)&ev[(long)w * 2]       = make_float2(p0, p1);
        *(float2*)&ev[((long)N + w) * 2] = make_float2(p2, p3);
        *(float2*)&out[(long)w * 2]      = make_float2(p4 + sb[0], p5 + sb[1]);
    }
}

// ================= ev-gather + global min (R10-proven) + PDL ================
__global__ void gatherev_min_kernel(const float* __restrict__ ev,
                                    float* __restrict__ out, int N)
{
    pdl_trigger();
    int n = blockIdx.x * blockDim.x + threadIdx.x;
    int beg = 0, end = 0;
    if (n < N) { beg = g_off[n]; end = g_off[n + 1]; }
    pdl_wait();   // ev / out written by gather2

    float m = 3.402823466e+38f;
    if (n < N) {
        float2 a0 = *(float2*)&out[n * 2];
        float2 a1 = make_float2(0.f, 0.f), a2 = a1, a3 = a1;
        int e = beg;
        for (; e + 4 <= end; e += 4) {
            unsigned p0 = g_elist[e],     p1 = g_elist[e + 1];
            unsigned p2 = g_elist[e + 2], p3 = g_elist[e + 3];
            float2 v0 = *(const float2*)&ev[(long)((p0 >> 16) * N + (p0 & 0xFFFFu)) * 2];
            float2 v1 = *(const float2*)&ev[(long)((p1 >> 16) * N + (p1 & 0xFFFFu)) * 2];
            float2 v2 = *(const float2*)&ev[(long)((p2 >> 16) * N + (p2 & 0xFFFFu)) * 2];
            float2 v3 = *(const float2*)&ev[(long)((p3 >> 16) * N + (p3 & 0xFFFFu)) * 2];
            a0.x += v0.x; a0.y += v0.y;
            a1.x += v1.x; a1.y += v1.y;
            a2.x += v2.x; a2.y += v2.y;
            a3.x += v3.x; a3.y += v3.y;
        }
        for (; e < end; e++) {
            unsigned p = g_elist[e];
            float2 v = *(const float2*)&ev[(long)((p >> 16) * N + (p & 0xFFFFu)) * 2];
            a0.x += v.x; a0.y += v.y;
        }
        a0.x += a1.x + a2.x + a3.x;
        a0.y += a1.y + a2.y + a3.y;
        *(float2*)&out[n * 2] = a0;
        m = fminf(a0.x, a0.y);
    }
    #pragma unroll
    for (int o = 16; o; o >>= 1)
        m = fminf(m, __shfl_xor_sync(0xffffffffu, m, o));
    __shared__ float sm[8];
    if ((threadIdx.x & 31) == 0) sm[threadIdx.x >> 5] = m;
    __syncthreads();
    if (threadIdx.x < 8) {
        m = sm[threadIdx.x];
        #pragma unroll
        for (int o = 4; o; o >>= 1)
            m = fminf(m, __shfl_xor_sync(0xffu, m, o));
        if (threadIdx.x == 0) atomicMin(&g_min_key, fenc(m));
    }
}

__global__ void mask_kernel(float* __restrict__ out,
                            const int* __restrict__ cs,
                            const int* __restrict__ ms, int N)
{
    pdl_wait();
    int n = blockIdx.x * blockDim.x + threadIdx.x;
    if (n >= N) return;
    float mn = fdec(g_min_key) - 1.0f;
    float2 v = *(float2*)&out[n * 2];
    if (cs[n] >= ms[n] - 1) v.x = mn;
    if (cs[n] == 0)         v.y = mn;
    *(float2*)&out[n * 2] = v;
}

// ================= launch =================
extern "C" void kernel_launch(void* const* d_in, const int* in_sizes, int n_in,
                              void* d_out, int out_size)
{
    const float* x  = (const float*)d_in[0];
    const int* src  = (const int*)d_in[1];
    const int* dst  = (const int*)d_in[2];
    const int* et   = (const int*)d_in[3];
    const int* cs   = (const int*)d_in[4];
    const int* ms   = (const int*)d_in[5];
    const float* W1 = (const float*)d_in[6];
    const float* L1 = (const float*)d_in[7];
    const float* b1 = (const float*)d_in[8];
    const float* W2 = (const float*)d_in[9];
    const float* L2 = (const float*)d_in[10];
    const float* b2 = (const float*)d_in[11];
    const float* W3 = (const float*)d_in[12];
    const float* L3 = (const float*)d_in[13];
    const float* b3 = (const float*)d_in[14];

    const int N = in_sizes[0] / 128;
    const int E = in_sizes[1];
    float* out = (float*)d_out;

    float *tx, *bufA, *bufB, *ev;
    __nv_bfloat16 *w1h, *w1l, *w2h, *w2l;
    cudaGetSymbolAddress((void**)&tx,   g_tx);
    cudaGetSymbolAddress((void**)&bufA, g_bufA);
    cudaGetSymbolAddress((void**)&bufB, g_bufB);
    cudaGetSymbolAddress((void**)&ev,   g_ev);
    cudaGetSymbolAddress((void**)&w1h,  g_w1h);
    cudaGetSymbolAddress((void**)&w1l,  g_w1l);
    cudaGetSymbolAddress((void**)&w2h,  g_w2h);
    cudaGetSymbolAddress((void**)&w2l,  g_w2l);

    constexpr int SMEM1 = (2 * 128 * (128 + 8) + 2 * 3 * 128 * 72) * 2;  // 180224
    constexpr int SMEM2 = (2 * 128 * (64 + 8)  + 2 * 3 * 64  * 72) * 2;  // 92160
    cudaFuncSetAttribute(gemm_tc2_kernel<128, false>,
                         cudaFuncAttributeMaxDynamicSharedMemorySize, SMEM1);
    cudaFuncSetAttribute(gemm_tc2_kernel<64, true>,
                         cudaFuncAttributeMaxDynamicSharedMemorySize, SMEM2);

    static cudaStream_t s2 = nullptr;
    static cudaEvent_t evFork = nullptr, evCSR = nullptr;
    if (!s2) {
        cudaStreamCreateWithFlags(&s2, cudaStreamNonBlocking);
        cudaEventCreateWithFlags(&evFork, cudaEventDisableTiming);
        cudaEventCreateWithFlags(&evCSR,  cudaEventDisableTiming);
    }

    const int numTiles = (N + 127) / 128;
    int nodeBlocks = (N + 255) / 256;
    int edgeBlocks = (E + 255) / 256;
    int gatherBlocks = (N * 32 + 255) / 256;
    int scanBlocks = (N + 1023) / 1024;

    cudaLaunchAttribute pdlAttr;
    pdlAttr.id = cudaLaunchAttributeProgrammaticStreamSerialization;
    pdlAttr.val.programmaticStreamSerializationAllowed = 1;
    auto mkcfg = [&](int g, int b, size_t smem) {
        cudaLaunchConfig_t c{};
        c.gridDim = dim3(g); c.blockDim = dim3(b);
        c.dynamicSmemBytes = smem; c.stream = 0;
        c.attrs = &pdlAttr; c.numAttrs = 1;
        return c;
    };

    // fork CSR branch immediately
    cudaEventRecord(evFork, 0);
    cudaStreamWaitEvent(s2, evFork, 0);

    // --- branch A (s2): CSR build (rank-based, atomic-free fill) ---
    setupB_kernel<<<nodeBlocks, 256, 0, s2>>>(N);
    hist_kernel<<<edgeBlocks, 256, 0, s2>>>(dst, E);
    scan_kernel<<<scanBlocks, 1024, 0, s2>>>(N, E);
    fill_kernel<<<edgeBlocks, 256, 0, s2>>>(src, dst, et, E);
    cudaEventRecord(evCSR, s2);

    // --- branch B (main): presplit + layer-1 GEMM ---
    setupA_kernel<<<(36864 + 255) / 256, 256>>>(W1, L1, W2, L2);
    gemm_tc2_kernel<128, false><<<numTiles, 512, SMEM1>>>(x, N,
        w1h, w1l, b1, tx, tx + (long)N * 64, bufA);

    // --- join + PDL chain ---
    cudaStreamWaitEvent(0, evCSR, 0);
    {
        cudaLaunchConfig_t c = mkcfg(gatherBlocks, 256, 0);
        cudaLaunchKernelEx(&c, gather64_kernel<false>,
            (const float*)tx, bufA, N,
            (const float*)nullptr, (const float*)nullptr, (const float*)nullptr,
            (float*)nullptr, (float*)nullptr);
    }
    {
        cudaLaunchConfig_t c = mkcfg(numTiles, 512, SMEM2);
        cudaLaunchKernelEx(&c, gemm_tc2_kernel<64, true>,
            (const float*)bufA, N,
            (const __nv_bfloat16*)w2h, (const __nv_bfloat16*)w2l, b2,
            tx, tx + (long)N * 64, bufB);
    }
    {
        cudaLaunchConfig_t c = mkcfg(gatherBlocks, 256, 0);
        cudaLaunchKernelEx(&c, gather64_kernel<true>,
            (const float*)tx, bufB, N, W3, L3, b3, ev, out);
    }
    {
        cudaLaunchConfig_t c = mkcfg(nodeBlocks, 256, 0);
        cudaLaunchKernelEx(&c, gatherev_min_kernel, (const float*)ev, out, N);
    }
    {
        cudaLaunchConfig_t c = mkcfg(nodeBlocks, 256, 0);
        cudaLaunchKernelEx(&c, mask_kernel, out, cs, ms, N);
    }
}

// round 16
// speedup vs baseline: 1.3019x; 1.0578x over previous
#include <cuda_runtime.h>
#include <cuda_bf16.h>
#include <cuda_fp16.h>
#include <cstdint>

#define MAX_N 50000
#define MAX_E 800000
#define HDIM  64

// ---------------- scratch (no allocations allowed) ----------------
__device__ __half g_tx[2L * MAX_N * HDIM];   // per-relation messages (fp16)
__device__ float g_bufA[MAX_N * HDIM];
__device__ float g_bufB[MAX_N * HDIM];
__device__ float g_ev[2L * MAX_N * 2];       // layer-3 messages stay fp32
__device__ int   g_cnt[MAX_N];
__device__ int   g_off[MAX_N + 1];
__device__ int   g_rank[MAX_E];
__device__ int   g_bsum[64];
__device__ unsigned g_elist[MAX_E];
__device__ unsigned g_min_key;
__device__ __nv_bfloat16 g_w1h[3 * 128 * 64], g_w1l[3 * 128 * 64];
__device__ __nv_bfloat16 g_w2h[3 * 64 * 64],  g_w2l[3 * 64 * 64];

__device__ __forceinline__ unsigned fenc(float f) {
    unsigned b = __float_as_uint(f);
    return (b & 0x80000000u) ? ~b : (b | 0x80000000u);
}
__device__ __forceinline__ float fdec(unsigned k) {
    unsigned b = (k & 0x80000000u) ? (k ^ 0x80000000u) : ~k;
    return __uint_as_float(b);
}
__device__ __forceinline__ void split_bf16(float v, __nv_bfloat16& h, __nv_bfloat16& l) {
    h = __float2bfloat16(v);
    l = __float2bfloat16(v - __bfloat162float(h));
}

// ---------------- PDL primitives ----------------
__device__ __forceinline__ void pdl_trigger() {
    asm volatile("griddepcontrol.launch_dependents;");
}
__device__ __forceinline__ void pdl_wait() {
    asm volatile("griddepcontrol.wait;" ::: "memory");
}

// ================= setup A: presplit weights (main stream) =================
__global__ void setupA_kernel(const float* __restrict__ W1, const float* __restrict__ L1,
                              const float* __restrict__ W2, const float* __restrict__ L2)
{
    int i = blockIdx.x * blockDim.x + threadIdx.x;
    if (i < 24576) {
        float v = (i < 16384) ? W1[i] : L1[i - 16384];
        split_bf16(v, g_w1h[i], g_w1l[i]);
    } else if (i < 36864) {
        int j = i - 24576;
        float v = (j < 8192) ? W2[j] : L2[j - 8192];
        split_bf16(v, g_w2h[j], g_w2l[j]);
    }
}

// ================= setup B: zero counters + sentinels (CSR stream) =========
__global__ void setupB_kernel(int N)
{
    int i = blockIdx.x * blockDim.x + threadIdx.x;
    if (i < N) g_cnt[i] = 0;
    if (i < 64) g_bsum[i] = -1;
    if (i == 0) g_min_key = 0xFFFFFFFFu;
}

// ================= CSR build (R15-proven rank-based) =================
__global__ void hist_kernel(const int* __restrict__ dst, int E) {
    int e = blockIdx.x * blockDim.x + threadIdx.x;
    if (e < E) g_rank[e] = atomicAdd(&g_cnt[dst[e]], 1);
}

__global__ void __launch_bounds__(1024) scan_kernel(int N, int E) {
    __shared__ int sa[1024], sb[1024];
    __shared__ int bpre;
    const int tid = threadIdx.x;
    const int i = blockIdx.x * 1024 + tid;
    int v = (i < N) ? g_cnt[i] : 0;
    sa[tid] = v;
    __syncthreads();
    int* in = sa; int* out = sb;
    #pragma unroll
    for (int o = 1; o < 1024; o <<= 1) {
        out[tid] = in[tid] + (tid >= o ? in[tid - o] : 0);
        __syncthreads();
        int* t = in; in = out; out = t;
    }
    if (tid == 1023)
        ((volatile int*)g_bsum)[blockIdx.x] = in[1023];
    if (tid < 32) {
        int run = 0;
        for (int base = 0; base < blockIdx.x; base += 32) {
            int idx = base + tid;
            int bv = 0;
            if (idx < blockIdx.x) {
                do { bv = ((volatile int*)g_bsum)[idx]; } while (bv < 0);
            }
            #pragma unroll
            for (int o = 16; o; o >>= 1) bv += __shfl_xor_sync(0xffffffffu, bv, o);
            run += bv;
        }
        if (tid == 0) bpre = run;
    }
    __syncthreads();
    if (i < N) g_off[i] = bpre + in[tid] - v;
    if (i == 0) g_off[N] = E;
}

__global__ void fill_kernel(const int* __restrict__ src,
                            const int* __restrict__ dst,
                            const int* __restrict__ et, int E) {
    int e = blockIdx.x * blockDim.x + threadIdx.x;
    if (e >= E) return;
    int p = g_off[dst[e]] + g_rank[e];
    g_elist[p] = (unsigned)src[e] | ((unsigned)et[e] << 16);
}

// ================= tensor-core helpers =================
__device__ __forceinline__ void ldsm_x4(uint32_t* r, const void* p) {
    uint32_t a = (uint32_t)__cvta_generic_to_shared(p);
    asm volatile("ldmatrix.sync.aligned.m8n8.x4.shared.b16 {%0,%1,%2,%3}, [%4];"
        : "=r"(r[0]), "=r"(r[1]), "=r"(r[2]), "=r"(r[3]) : "r"(a));
}
__device__ __forceinline__ void ldsm_x2t(uint32_t* r, const void* p) {
    uint32_t a = (uint32_t)__cvta_generic_to_shared(p);
    asm volatile("ldmatrix.sync.aligned.m8n8.x2.trans.shared.b16 {%0,%1}, [%2];"
        : "=r"(r[0]), "=r"(r[1]) : "r"(a));
}
__device__ __forceinline__ void mma_bf16(float* c, const uint32_t* a, const uint32_t* b) {
    asm volatile("mma.sync.aligned.m16n8k16.row.col.f32.bf16.bf16.f32 "
        "{%0,%1,%2,%3}, {%4,%5,%6,%7}, {%8,%9}, {%0,%1,%2,%3};"
        : "+f"(c[0]), "+f"(c[1]), "+f"(c[2]), "+f"(c[3])
        : "r"(a[0]), "r"(a[1]), "r"(a[2]), "r"(a[3]), "r"(b[0]), "r"(b[1]));
}

// ================= tensor-core triple GEMM (R7-proven) + PDL ==============
// Relation outputs C0/C1 stored fp16 (message buffers); self-loop Cl fp32.
template<int K, bool RELU_IN>
__global__ void __launch_bounds__(512, 1) gemm_tc2_kernel(
    const float* __restrict__ A, int M,
    const __nv_bfloat16* __restrict__ Wh, const __nv_bfloat16* __restrict__ Wl,
    const float* __restrict__ bias,
    __half* __restrict__ C0, __half* __restrict__ C1, float* __restrict__ Cl)
{
    constexpr int BM = 128;
    constexpr int AS = K + 8;
    constexpr int WS = 72;
    extern __shared__ __nv_bfloat16 sm[];
    __nv_bfloat16* Ahi = sm;
    __nv_bfloat16* Alo = Ahi + BM * AS;
    __nv_bfloat16* Whs = Alo + BM * AS;
    __nv_bfloat16* Wls = Whs + 3 * K * WS;

    const int tid  = threadIdx.x;
    const int lane = tid & 31;
    const int warp = tid >> 5;
    const int rowBase = blockIdx.x * BM;

    pdl_trigger();

    for (int u = tid; u < 3 * K * 8; u += 512) {
        int row = u >> 3, col = (u & 7) * 8;
        *(uint4*)&Whs[row * WS + col] = *(const uint4*)&Wh[row * 64 + col];
        *(uint4*)&Wls[row * WS + col] = *(const uint4*)&Wl[row * 64 + col];
    }

    if (K == 64) pdl_wait();   // gemm2: A comes from gather1 (immediate pred)

    for (int i = tid * 4; i < BM * K; i += 2048) {
        int r = i / K, kq = i % K;
        float4 v = make_float4(0.f, 0.f, 0.f, 0.f);
        if (rowBase + r < M) v = *(const float4*)&A[(long)(rowBase + r) * K + kq];
        float vv[4] = {v.x, v.y, v.z, v.w};
        #pragma unroll
        for (int j = 0; j < 4; j++) {
            float x = RELU_IN ? fmaxf(vv[j], 0.f) : vv[j];
            __nv_bfloat16 h, l;
            split_bf16(x, h, l);
            Ahi[r * AS + kq + j] = h;
            Alo[r * AS + kq + j] = l;
        }
    }
    __syncthreads();

    const int mw = (warp & 3) * 32;
    const int nw = (warp >> 2) * 48;
    const int lr = lane & 15;
    const int aCol = (lane >> 4) * 8;

    float acc[2][6][4];
    #pragma unroll
    for (int mt = 0; mt < 2; mt++)
        #pragma unroll
        for (int j = 0; j < 6; j++)
            #pragma unroll
            for (int q = 0; q < 4; q++) acc[mt][j][q] = 0.f;

    #pragma unroll
    for (int kk = 0; kk < K / 16; kk++) {
        uint32_t ah[2][4], al[2][4];
        #pragma unroll
        for (int mt = 0; mt < 2; mt++) {
            ldsm_x4(ah[mt], &Ahi[(mw + mt * 16 + lr) * AS + kk * 16 + aCol]);
            ldsm_x4(al[mt], &Alo[(mw + mt * 16 + lr) * AS + kk * 16 + aCol]);
        }
        #pragma unroll
        for (int j = 0; j < 6; j++) {
            int n = nw + j * 8;
            int w = n >> 6, nc = n & 63;
            long woff = (long)(w * K + kk * 16 + lr) * WS + nc;
            uint32_t bh[2], bl[2];
            ldsm_x2t(bh, &Whs[woff]);
            ldsm_x2t(bl, &Wls[woff]);
            mma_bf16(acc[0][j], ah[0], bh);
            mma_bf16(acc[0][j], ah[0], bl);
            mma_bf16(acc[0][j], al[0], bh);
            mma_bf16(acc[1][j], ah[1], bh);
            mma_bf16(acc[1][j], ah[1], bl);
            mma_bf16(acc[1][j], al[1], bh);
        }
    }

    #pragma unroll
    for (int mt = 0; mt < 2; mt++) {
        const int r0 = rowBase + mw + mt * 16 + (lane >> 2);
        #pragma unroll
        for (int j = 0; j < 6; j++) {
            int n = nw + j * 8;
            int w = n >> 6;
            int nc = (n & 63) + 2 * (lane & 3);
            if (w == 2) {
                float b0 = bias[nc], b1 = bias[nc + 1];
                if (r0 < M)
                    *(float2*)&Cl[(long)r0 * 64 + nc] =
                        make_float2(acc[mt][j][0] + b0, acc[mt][j][1] + b1);
                if (r0 + 8 < M)
                    *(float2*)&Cl[(long)(r0 + 8) * 64 + nc] =
                        make_float2(acc[mt][j][2] + b0, acc[mt][j][3] + b1);
            } else {
                __half* Cp = w ? C1 : C0;
                if (r0 < M)
                    *(__half2*)&Cp[(long)r0 * 64 + nc] =
                        __floats2half2_rn(acc[mt][j][0], acc[mt][j][1]);
                if (r0 + 8 < M)
                    *(__half2*)&Cp[(long)(r0 + 8) * 64 + nc] =
                        __floats2half2_rn(acc[mt][j][2], acc[mt][j][3]);
            }
        }
    }
}

// ================= gather64 (R10-champion loop, fp16 messages) + PDL ========
template<bool FINAL>
__global__ void gather64_kernel(const __half* __restrict__ t,
                                float* __restrict__ agg, int N,
                                const float* __restrict__ W3,
                                const float* __restrict__ L3,
                                const float* __restrict__ b3,
                                float* __restrict__ ev,
                                float* __restrict__ out)
{
    pdl_trigger();

    __shared__ float sW0[128], sW1[128], sL[128], sb[2];
    if (FINAL) {
        int tid = threadIdx.x;
        for (int i = tid; i < 128; i += blockDim.x) {
            sW0[i] = W3[i];
            sW1[i] = W3[128 + i];
            sL[i]  = L3[i];
        }
        if (tid < 2) sb[tid] = b3[tid];
        __syncthreads();
    }

    int w = (int)((blockIdx.x * (long)blockDim.x + threadIdx.x) >> 5);
    int lane = threadIdx.x & 31;
    if (w >= N) return;
    int beg = g_off[w], end = g_off[w + 1];

    pdl_wait();   // agg / t written by immediate predecessor

    long o = (long)w * 64 + lane * 2;
    float2 a0 = *(float2*)&agg[o];
    float2 a1 = make_float2(0.f, 0.f), a2 = a1, a3 = a1;
    int e = beg;
    for (; e + 4 <= end; e += 4) {
        unsigned p0 = g_elist[e],     p1 = g_elist[e + 1];
        unsigned p2 = g_elist[e + 2], p3 = g_elist[e + 3];
        float2 v0 = __half22float2(*(const __half2*)&t[(long)((p0 >> 16) * N + (p0 & 0xFFFFu)) * 64 + lane * 2]);
        float2 v1 = __half22float2(*(const __half2*)&t[(long)((p1 >> 16) * N + (p1 & 0xFFFFu)) * 64 + lane * 2]);
        float2 v2 = __half22float2(*(const __half2*)&t[(long)((p2 >> 16) * N + (p2 & 0xFFFFu)) * 64 + lane * 2]);
        float2 v3 = __half22float2(*(const __half2*)&t[(long)((p3 >> 16) * N + (p3 & 0xFFFFu)) * 64 + lane * 2]);
        a0.x += v0.x; a0.y += v0.y;
        a1.x += v1.x; a1.y += v1.y;
        a2.x += v2.x; a2.y += v2.y;
        a3.x += v3.x; a3.y += v3.y;
    }
    for (; e < end; e++) {
        unsigned p = g_elist[e];
        float2 v = __half22float2(*(const __half2*)&t[(long)((p >> 16) * N + (p & 0xFFFFu)) * 64 + lane * 2]);
        a0.x += v.x; a0.y += v.y;
    }
    a0.x += a1.x + a2.x + a3.x;
    a0.y += a1.y + a2.y + a3.y;

    if (!FINAL) {
        *(float2*)&agg[o] = a0;
        return;
    }

    float x0 = fmaxf(a0.x, 0.f), x1 = fmaxf(a0.y, 0.f);
    int k0 = lane * 2, k1 = lane * 2 + 1;
    float p0 = x0 * sW0[k0 * 2 + 0] + x1 * sW0[k1 * 2 + 0];
    float p1 = x0 * sW0[k0 * 2 + 1] + x1 * sW0[k1 * 2 + 1];
    float p2 = x0 * sW1[k0 * 2 + 0] + x1 * sW1[k1 * 2 + 0];
    float p3 = x0 * sW1[k0 * 2 + 1] + x1 * sW1[k1 * 2 + 1];
    float p4 = x0 * sL[k0 * 2 + 0]  + x1 * sL[k1 * 2 + 0];
    float p5 = x0 * sL[k0 * 2 + 1]  + x1 * sL[k1 * 2 + 1];
    #pragma unroll
    for (int off = 16; off; off >>= 1) {
        p0 += __shfl_xor_sync(0xffffffffu, p0, off);
        p1 += __shfl_xor_sync(0xffffffffu, p1, off);
        p2 += __shfl_xor_sync(0xffffffffu, p2, off);
        p3 += __shfl_xor_sync(0xffffffffu, p3, off);
        p4 += __shfl_xor_sync(0xffffffffu, p4, off);
        p5 += __shfl_xor_sync(0xffffffffu, p5, off);
    }
    if (lane == 0) {
        *(float2*)&ev[(long)w * 2]       = make_float2(p0, p1);
        *(float2*)&ev[((long)N + w) * 2] = make_float2(p2, p3);
        *(float2*)&out[(long)w * 2]      = make_float2(p4 + sb[0], p5 + sb[1]);
    }
}

// ================= ev-gather + global min (R10-proven, ev fp32) + PDL =======
__global__ void gatherev_min_kernel(const float* __restrict__ ev,
                                    float* __restrict__ out, int N)
{
    pdl_trigger();
    int n = blockIdx.x * blockDim.x + threadIdx.x;
    int beg = 0, end = 0;
    if (n < N) { beg = g_off[n]; end = g_off[n + 1]; }
    pdl_wait();   // ev / out written by gather2

    float m = 3.402823466e+38f;
    if (n < N) {
        float2 a0 = *(float2*)&out[n * 2];
        float2 a1 = make_float2(0.f, 0.f), a2 = a1, a3 = a1;
        int e = beg;
        for (; e + 4 <= end; e += 4) {
            unsigned p0 = g_elist[e],     p1 = g_elist[e + 1];
            unsigned p2 = g_elist[e + 2], p3 = g_elist[e + 3];
            float2 v0 = *(const float2*)&ev[(long)((p0 >> 16) * N + (p0 & 0xFFFFu)) * 2];
            float2 v1 = *(const float2*)&ev[(long)((p1 >> 16) * N + (p1 & 0xFFFFu)) * 2];
            float2 v2 = *(const float2*)&ev[(long)((p2 >> 16) * N + (p2 & 0xFFFFu)) * 2];
            float2 v3 = *(const float2*)&ev[(long)((p3 >> 16) * N + (p3 & 0xFFFFu)) * 2];
            a0.x += v0.x; a0.y += v0.y;
            a1.x += v1.x; a1.y += v1.y;
            a2.x += v2.x; a2.y += v2.y;
            a3.x += v3.x; a3.y += v3.y;
        }
        for (; e < end; e++) {
            unsigned p = g_elist[e];
            float2 v = *(const float2*)&ev[(long)((p >> 16) * N + (p & 0xFFFFu)) * 2];
            a0.x += v.x; a0.y += v.y;
        }
        a0.x += a1.x + a2.x + a3.x;
        a0.y += a1.y + a2.y + a3.y;
        *(float2*)&out[n * 2] = a0;
        m = fminf(a0.x, a0.y);
    }
    #pragma unroll
    for (int o = 16; o; o >>= 1)
        m = fminf(m, __shfl_xor_sync(0xffffffffu, m, o));
    __shared__ float sm[8];
    if ((threadIdx.x & 31) == 0) sm[threadIdx.x >> 5] = m;
    __syncthreads();
    if (threadIdx.x < 8) {
        m = sm[threadIdx.x];
        #pragma unroll
        for (int o = 4; o; o >>= 1)
            m = fminf(m, __shfl_xor_sync(0xffu, m, o));
        if (threadIdx.x == 0) atomicMin(&g_min_key, fenc(m));
    }
}

__global__ void mask_kernel(float* __restrict__ out,
                            const int* __restrict__ cs,
                            const int* __restrict__ ms, int N)
{
    pdl_wait();
    int n = blockIdx.x * blockDim.x + threadIdx.x;
    if (n >= N) return;
    float mn = fdec(g_min_key) - 1.0f;
    float2 v = *(float2*)&out[n * 2];
    if (cs[n] >= ms[n] - 1) v.x = mn;
    if (cs[n] == 0)         v.y = mn;
    *(float2*)&out[n * 2] = v;
}

// ================= launch =================
extern "C" void kernel_launch(void* const* d_in, const int* in_sizes, int n_in,
                              void* d_out, int out_size)
{
    const float* x  = (const float*)d_in[0];
    const int* src  = (const int*)d_in[1];
    const int* dst  = (const int*)d_in[2];
    const int* et   = (const int*)d_in[3];
    const int* cs   = (const int*)d_in[4];
    const int* ms   = (const int*)d_in[5];
    const float* W1 = (const float*)d_in[6];
    const float* L1 = (const float*)d_in[7];
    const float* b1 = (const float*)d_in[8];
    const float* W2 = (const float*)d_in[9];
    const float* L2 = (const float*)d_in[10];
    const float* b2 = (const float*)d_in[11];
    const float* W3 = (const float*)d_in[12];
    const float* L3 = (const float*)d_in[13];
    const float* b3 = (const float*)d_in[14];

    const int N = in_sizes[0] / 128;
    const int E = in_sizes[1];
    float* out = (float*)d_out;

    __half* tx;
    float *bufA, *bufB, *ev;
    __nv_bfloat16 *w1h, *w1l, *w2h, *w2l;
    cudaGetSymbolAddress((void**)&tx,   g_tx);
    cudaGetSymbolAddress((void**)&bufA, g_bufA);
    cudaGetSymbolAddress((void**)&bufB, g_bufB);
    cudaGetSymbolAddress((void**)&ev,   g_ev);
    cudaGetSymbolAddress((void**)&w1h,  g_w1h);
    cudaGetSymbolAddress((void**)&w1l,  g_w1l);
    cudaGetSymbolAddress((void**)&w2h,  g_w2h);
    cudaGetSymbolAddress((void**)&w2l,  g_w2l);

    constexpr int SMEM1 = (2 * 128 * (128 + 8) + 2 * 3 * 128 * 72) * 2;  // 180224
    constexpr int SMEM2 = (2 * 128 * (64 + 8)  + 2 * 3 * 64  * 72) * 2;  // 92160
    cudaFuncSetAttribute(gemm_tc2_kernel<128, false>,
                         cudaFuncAttributeMaxDynamicSharedMemorySize, SMEM1);
    cudaFuncSetAttribute(gemm_tc2_kernel<64, true>,
                         cudaFuncAttributeMaxDynamicSharedMemorySize, SMEM2);

    static cudaStream_t s2 = nullptr;
    static cudaEvent_t evFork = nullptr, evCSR = nullptr;
    if (!s2) {
        cudaStreamCreateWithFlags(&s2, cudaStreamNonBlocking);
        cudaEventCreateWithFlags(&evFork, cudaEventDisableTiming);
        cudaEventCreateWithFlags(&evCSR,  cudaEventDisableTiming);
    }

    const int numTiles = (N + 127) / 128;
    int nodeBlocks = (N + 255) / 256;
    int edgeBlocks = (E + 255) / 256;
    int gatherBlocks = (N * 32 + 255) / 256;
    int scanBlocks = (N + 1023) / 1024;

    cudaLaunchAttribute pdlAttr;
    pdlAttr.id = cudaLaunchAttributeProgrammaticStreamSerialization;
    pdlAttr.val.programmaticStreamSerializationAllowed = 1;
    auto mkcfg = [&](int g, int b, size_t smem) {
        cudaLaunchConfig_t c{};
        c.gridDim = dim3(g); c.blockDim = dim3(b);
        c.dynamicSmemBytes = smem; c.stream = 0;
        c.attrs = &pdlAttr; c.numAttrs = 1;
        return c;
    };

    // fork CSR branch immediately
    cudaEventRecord(evFork, 0);
    cudaStreamWaitEvent(s2, evFork, 0);

    // --- branch A (s2): CSR build (rank-based, atomic-free fill) ---
    setupB_kernel<<<nodeBlocks, 256, 0, s2>>>(N);
    hist_kernel<<<edgeBlocks, 256, 0, s2>>>(dst, E);
    scan_kernel<<<scanBlocks, 1024, 0, s2>>>(N, E);
    fill_kernel<<<edgeBlocks, 256, 0, s2>>>(src, dst, et, E);
    cudaEventRecord(evCSR, s2);

    // --- branch B (main): presplit + layer-1 GEMM ---
    setupA_kernel<<<(36864 + 255) / 256, 256>>>(W1, L1, W2, L2);
    gemm_tc2_kernel<128, false><<<numTiles, 512, SMEM1>>>(x, N,
        w1h, w1l, b1, tx, tx + (long)N * 64, bufA);

    // --- join + PDL chain ---
    cudaStreamWaitEvent(0, evCSR, 0);
    {
        cudaLaunchConfig_t c = mkcfg(gatherBlocks, 256, 0);
        cudaLaunchKernelEx(&c, gather64_kernel<false>,
            (const __half*)tx, bufA, N,
            (const float*)nullptr, (const float*)nullptr, (const float*)nullptr,
            (float*)nullptr, (float*)nullptr);
    }
    {
        cudaLaunchConfig_t c = mkcfg(numTiles, 512, SMEM2);
        cudaLaunchKernelEx(&c, gemm_tc2_kernel<64, true>,
            (const float*)bufA, N,
            (const __nv_bfloat16*)w2h, (const __nv_bfloat16*)w2l, b2,
            tx, tx + (long)N * 64, bufB);
    }
    {
        cudaLaunchConfig_t c = mkcfg(gatherBlocks, 256, 0);
        cudaLaunchKernelEx(&c, gather64_kernel<true>,
            (const __half*)tx, bufB, N, W3, L3, b3, ev, out);
    }
    {
        cudaLaunchConfig_t c = mkcfg(nodeBlocks, 256, 0);
        cudaLaunchKernelEx(&c, gatherev_min_kernel, (const float*)ev, out, N);
    }
    {
        cudaLaunchConfig_t c = mkcfg(nodeBlocks, 256, 0);
        cudaLaunchKernelEx(&c, mask_kernel, out, cs, ms, N);
    }
}

// round 17
// speedup vs baseline: 1.3163x; 1.0110x over previous
#include <cuda_runtime.h>
#include <cuda_bf16.h>
#include <cuda_fp16.h>
#include <cstdint>

#define MAX_N 50000
#define MAX_E 800000
#define HDIM  64

// ---------------- scratch (no allocations allowed) ----------------
__device__ __half g_tx[2L * MAX_N * HDIM];   // per-relation messages (fp16)
__device__ float g_bufA[MAX_N * HDIM];
__device__ float g_bufB[MAX_N * HDIM];
__device__ float g_ev[2L * MAX_N * 2];
__device__ int   g_cnt[MAX_N];
__device__ int   g_off[MAX_N + 1];
__device__ int   g_rank[MAX_E];
__device__ int   g_bsum[64];
__device__ unsigned g_elist[MAX_E];
__device__ unsigned g_min_key;
__device__ __nv_bfloat16 g_w1h[3 * 128 * 64], g_w1l[3 * 128 * 64];
__device__ __nv_bfloat16 g_w2h[3 * 64 * 64],  g_w2l[3 * 64 * 64];

__device__ __forceinline__ unsigned fenc(float f) {
    unsigned b = __float_as_uint(f);
    return (b & 0x80000000u) ? ~b : (b | 0x80000000u);
}
__device__ __forceinline__ float fdec(unsigned k) {
    unsigned b = (k & 0x80000000u) ? (k ^ 0x80000000u) : ~k;
    return __uint_as_float(b);
}
__device__ __forceinline__ void split_bf16(float v, __nv_bfloat16& h, __nv_bfloat16& l) {
    h = __float2bfloat16(v);
    l = __float2bfloat16(v - __bfloat162float(h));
}

// ---------------- PDL primitives ----------------
__device__ __forceinline__ void pdl_trigger() {
    asm volatile("griddepcontrol.launch_dependents;");
}
__device__ __forceinline__ void pdl_wait() {
    asm volatile("griddepcontrol.wait;" ::: "memory");
}

// ================= setup A: presplit weights (main stream) =================
__global__ void setupA_kernel(const float* __restrict__ W1, const float* __restrict__ L1,
                              const float* __restrict__ W2, const float* __restrict__ L2)
{
    int i = blockIdx.x * blockDim.x + threadIdx.x;
    if (i < 24576) {
        float v = (i < 16384) ? W1[i] : L1[i - 16384];
        split_bf16(v, g_w1h[i], g_w1l[i]);
    } else if (i < 36864) {
        int j = i - 24576;
        float v = (j < 8192) ? W2[j] : L2[j - 8192];
        split_bf16(v, g_w2h[j], g_w2l[j]);
    }
}

// ================= setup B: zero counters + sentinels (CSR stream) =========
__global__ void setupB_kernel(int N)
{
    int i = blockIdx.x * blockDim.x + threadIdx.x;
    if (i < N) g_cnt[i] = 0;
    if (i < 64) g_bsum[i] = -1;
    if (i == 0) g_min_key = 0xFFFFFFFFu;
}

// ================= CSR build (R15-proven rank-based) =================
__global__ void hist_kernel(const int* __restrict__ dst, int E) {
    int e = blockIdx.x * blockDim.x + threadIdx.x;
    if (e < E) g_rank[e] = atomicAdd(&g_cnt[dst[e]], 1);
}

__global__ void __launch_bounds__(1024) scan_kernel(int N, int E) {
    __shared__ int sa[1024], sb[1024];
    __shared__ int bpre;
    const int tid = threadIdx.x;
    const int i = blockIdx.x * 1024 + tid;
    int v = (i < N) ? g_cnt[i] : 0;
    sa[tid] = v;
    __syncthreads();
    int* in = sa; int* out = sb;
    #pragma unroll
    for (int o = 1; o < 1024; o <<= 1) {
        out[tid] = in[tid] + (tid >= o ? in[tid - o] : 0);
        __syncthreads();
        int* t = in; in = out; out = t;
    }
    if (tid == 1023)
        ((volatile int*)g_bsum)[blockIdx.x] = in[1023];
    if (tid < 32) {
        int run = 0;
        for (int base = 0; base < blockIdx.x; base += 32) {
            int idx = base + tid;
            int bv = 0;
            if (idx < blockIdx.x) {
                do { bv = ((volatile int*)g_bsum)[idx]; } while (bv < 0);
            }
            #pragma unroll
            for (int o = 16; o; o >>= 1) bv += __shfl_xor_sync(0xffffffffu, bv, o);
            run += bv;
        }
        if (tid == 0) bpre = run;
    }
    __syncthreads();
    if (i < N) g_off[i] = bpre + in[tid] - v;
    if (i == 0) g_off[N] = E;
}

__global__ void fill_kernel(const int* __restrict__ src,
                            const int* __restrict__ dst,
                            const int* __restrict__ et, int E) {
    int e = blockIdx.x * blockDim.x + threadIdx.x;
    if (e >= E) return;
    int p = g_off[dst[e]] + g_rank[e];
    g_elist[p] = (unsigned)src[e] | ((unsigned)et[e] << 16);
}

// ================= tensor-core helpers =================
__device__ __forceinline__ void ldsm_x4(uint32_t* r, const void* p) {
    uint32_t a = (uint32_t)__cvta_generic_to_shared(p);
    asm volatile("ldmatrix.sync.aligned.m8n8.x4.shared.b16 {%0,%1,%2,%3}, [%4];"
        : "=r"(r[0]), "=r"(r[1]), "=r"(r[2]), "=r"(r[3]) : "r"(a));
}
__device__ __forceinline__ void ldsm_x2t(uint32_t* r, const void* p) {
    uint32_t a = (uint32_t)__cvta_generic_to_shared(p);
    asm volatile("ldmatrix.sync.aligned.m8n8.x2.trans.shared.b16 {%0,%1}, [%2];"
        : "=r"(r[0]), "=r"(r[1]) : "r"(a));
}
__device__ __forceinline__ void mma_bf16(float* c, const uint32_t* a, const uint32_t* b) {
    asm volatile("mma.sync.aligned.m16n8k16.row.col.f32.bf16.bf16.f32 "
        "{%0,%1,%2,%3}, {%4,%5,%6,%7}, {%8,%9}, {%0,%1,%2,%3};"
        : "+f"(c[0]), "+f"(c[1]), "+f"(c[2]), "+f"(c[3])
        : "r"(a[0]), "r"(a[1]), "r"(a[2]), "r"(a[3]), "r"(b[0]), "r"(b[1]));
}

// ================= GEMM v4: one weight matrix per CTA (2 CTAs/SM) ===========
// grid = (numTiles, 3); blockIdx.y selects the weight matrix. Smem per CTA:
// A(hi/lo) + ONE W(hi/lo) => 106KB (K=128) / 55KB (K=64) -> 2 CTAs co-resident.
// Warp tile 32x16 (4 M-warps x 4 N-warps, 2 j-tiles). Regs capped at 64.
template<int K, bool RELU_IN>
__global__ void __launch_bounds__(512, 2) gemm_tc3_kernel(
    const float* __restrict__ A, int M,
    const __nv_bfloat16* __restrict__ Wh, const __nv_bfloat16* __restrict__ Wl,
    const float* __restrict__ bias,
    __half* __restrict__ C0, __half* __restrict__ C1, float* __restrict__ Cl)
{
    constexpr int BM = 128;
    constexpr int AS = K + 8;
    constexpr int WS = 72;
    extern __shared__ __nv_bfloat16 sm[];
    __nv_bfloat16* Ahi = sm;                    // [BM][AS]
    __nv_bfloat16* Alo = Ahi + BM * AS;
    __nv_bfloat16* Whs = Alo + BM * AS;         // [K][WS]  (one matrix)
    __nv_bfloat16* Wls = Whs + K * WS;

    const int tid  = threadIdx.x;
    const int lane = tid & 31;
    const int warp = tid >> 5;
    const int rowBase = blockIdx.x * BM;
    const int wsel = blockIdx.y;

    pdl_trigger();

    // weight copy: only this CTA's matrix (pre-wait safe: setupA, 2 kernels old)
    for (int u = tid; u < K * 8; u += 512) {
        int row = u >> 3, col = (u & 7) * 8;
        *(uint4*)&Whs[row * WS + col] = *(const uint4*)&Wh[((long)wsel * K + row) * 64 + col];
        *(uint4*)&Wls[row * WS + col] = *(const uint4*)&Wl[((long)wsel * K + row) * 64 + col];
    }

    if (K == 64) pdl_wait();   // gemm2: A comes from gather1 (immediate pred)

    for (int i = tid * 4; i < BM * K; i += 2048) {
        int r = i / K, kq = i % K;
        float4 v = make_float4(0.f, 0.f, 0.f, 0.f);
        if (rowBase + r < M) v = *(const float4*)&A[(long)(rowBase + r) * K + kq];
        float vv[4] = {v.x, v.y, v.z, v.w};
        #pragma unroll
        for (int j = 0; j < 4; j++) {
            float x = RELU_IN ? fmaxf(vv[j], 0.f) : vv[j];
            __nv_bfloat16 h, l;
            split_bf16(x, h, l);
            Ahi[r * AS + kq + j] = h;
            Alo[r * AS + kq + j] = l;
        }
    }
    __syncthreads();

    // 4 warps in M (32 rows each), 4 warps in N (16 cols each)
    const int mw = (warp & 3) * 32;
    const int nw = (warp >> 2) * 16;
    const int lr = lane & 15;
    const int aCol = (lane >> 4) * 8;

    float acc[2][2][4];
    #pragma unroll
    for (int mt = 0; mt < 2; mt++)
        #pragma unroll
        for (int j = 0; j < 2; j++)
            #pragma unroll
            for (int q = 0; q < 4; q++) acc[mt][j][q] = 0.f;

    #pragma unroll
    for (int kk = 0; kk < K / 16; kk++) {
        uint32_t ah[2][4], al[2][4];
        #pragma unroll
        for (int mt = 0; mt < 2; mt++) {
            ldsm_x4(ah[mt], &Ahi[(mw + mt * 16 + lr) * AS + kk * 16 + aCol]);
            ldsm_x4(al[mt], &Alo[(mw + mt * 16 + lr) * AS + kk * 16 + aCol]);
        }
        #pragma unroll
        for (int j = 0; j < 2; j++) {
            int nc = nw + j * 8;
            long woff = (long)(kk * 16 + lr) * WS + nc;
            uint32_t bh[2], bl[2];
            ldsm_x2t(bh, &Whs[woff]);
            ldsm_x2t(bl, &Wls[woff]);
            mma_bf16(acc[0][j], ah[0], bh);
            mma_bf16(acc[0][j], ah[0], bl);
            mma_bf16(acc[0][j], al[0], bh);
            mma_bf16(acc[1][j], ah[1], bh);
            mma_bf16(acc[1][j], ah[1], bl);
            mma_bf16(acc[1][j], al[1], bh);
        }
    }

    #pragma unroll
    for (int mt = 0; mt < 2; mt++) {
        const int r0 = rowBase + mw + mt * 16 + (lane >> 2);
        #pragma unroll
        for (int j = 0; j < 2; j++) {
            int nc = nw + j * 8 + 2 * (lane & 3);
            if (wsel == 2) {
                float b0 = bias[nc], b1 = bias[nc + 1];
                if (r0 < M)
                    *(float2*)&Cl[(long)r0 * 64 + nc] =
                        make_float2(acc[mt][j][0] + b0, acc[mt][j][1] + b1);
                if (r0 + 8 < M)
                    *(float2*)&Cl[(long)(r0 + 8) * 64 + nc] =
                        make_float2(acc[mt][j][2] + b0, acc[mt][j][3] + b1);
            } else {
                __half* Cp = wsel ? C1 : C0;
                if (r0 < M)
                    *(__half2*)&Cp[(long)r0 * 64 + nc] =
                        __floats2half2_rn(acc[mt][j][0], acc[mt][j][1]);
                if (r0 + 8 < M)
                    *(__half2*)&Cp[(long)(r0 + 8) * 64 + nc] =
                        __floats2half2_rn(acc[mt][j][2], acc[mt][j][3]);
            }
        }
    }
}

// ================= gather64 (R16-champion, fp16 messages) + PDL =============
template<bool FINAL>
__global__ void gather64_kernel(const __half* __restrict__ t,
                                float* __restrict__ agg, int N,
                                const float* __restrict__ W3,
                                const float* __restrict__ L3,
                                const float* __restrict__ b3,
                                float* __restrict__ ev,
                                float* __restrict__ out)
{
    pdl_trigger();

    __shared__ float sW0[128], sW1[128], sL[128], sb[2];
    if (FINAL) {
        int tid = threadIdx.x;
        for (int i = tid; i < 128; i += blockDim.x) {
            sW0[i] = W3[i];
            sW1[i] = W3[128 + i];
            sL[i]  = L3[i];
        }
        if (tid < 2) sb[tid] = b3[tid];
        __syncthreads();
    }

    int w = (int)((blockIdx.x * (long)blockDim.x + threadIdx.x) >> 5);
    int lane = threadIdx.x & 31;
    if (w >= N) return;
    int beg = g_off[w], end = g_off[w + 1];

    pdl_wait();   // agg / t written by immediate predecessor

    long o = (long)w * 64 + lane * 2;
    float2 a0 = *(float2*)&agg[o];
    float2 a1 = make_float2(0.f, 0.f), a2 = a1, a3 = a1;
    int e = beg;
    for (; e + 4 <= end; e += 4) {
        unsigned p0 = g_elist[e],     p1 = g_elist[e + 1];
        unsigned p2 = g_elist[e + 2], p3 = g_elist[e + 3];
        float2 v0 = __half22float2(*(const __half2*)&t[(long)((p0 >> 16) * N + (p0 & 0xFFFFu)) * 64 + lane * 2]);
        float2 v1 = __half22float2(*(const __half2*)&t[(long)((p1 >> 16) * N + (p1 & 0xFFFFu)) * 64 + lane * 2]);
        float2 v2 = __half22float2(*(const __half2*)&t[(long)((p2 >> 16) * N + (p2 & 0xFFFFu)) * 64 + lane * 2]);
        float2 v3 = __half22float2(*(const __half2*)&t[(long)((p3 >> 16) * N + (p3 & 0xFFFFu)) * 64 + lane * 2]);
        a0.x += v0.x; a0.y += v0.y;
        a1.x += v1.x; a1.y += v1.y;
        a2.x += v2.x; a2.y += v2.y;
        a3.x += v3.x; a3.y += v3.y;
    }
    for (; e < end; e++) {
        unsigned p = g_elist[e];
        float2 v = __half22float2(*(const __half2*)&t[(long)((p >> 16) * N + (p & 0xFFFFu)) * 64 + lane * 2]);
        a0.x += v.x; a0.y += v.y;
    }
    a0.x += a1.x + a2.x + a3.x;
    a0.y += a1.y + a2.y + a3.y;

    if (!FINAL) {
        *(float2*)&agg[o] = a0;
        return;
    }

    float x0 = fmaxf(a0.x, 0.f), x1 = fmaxf(a0.y, 0.f);
    int k0 = lane * 2, k1 = lane * 2 + 1;
    float p0 = x0 * sW0[k0 * 2 + 0] + x1 * sW0[k1 * 2 + 0];
    float p1 = x0 * sW0[k0 * 2 + 1] + x1 * sW0[k1 * 2 + 1];
    float p2 = x0 * sW1[k0 * 2 + 0] + x1 * sW1[k1 * 2 + 0];
    float p3 = x0 * sW1[k0 * 2 + 1] + x1 * sW1[k1 * 2 + 1];
    float p4 = x0 * sL[k0 * 2 + 0]  + x1 * sL[k1 * 2 + 0];
    float p5 = x0 * sL[k0 * 2 + 1]  + x1 * sL[k1 * 2 + 1];
    #pragma unroll
    for (int off = 16; off; off >>= 1) {
        p0 += __shfl_xor_sync(0xffffffffu, p0, off);
        p1 += __shfl_xor_sync(0xffffffffu, p1, off);
        p2 += __shfl_xor_sync(0xffffffffu, p2, off);
        p3 += __shfl_xor_sync(0xffffffffu, p3, off);
        p4 += __shfl_xor_sync(0xffffffffu, p4, off);
        p5 += __shfl_xor_sync(0xffffffffu, p5, off);
    }
    if (lane == 0) {
        *(float2*)&ev[(long)w * 2]       = make_float2(p0, p1);
        *(float2*)&ev[((long)N + w) * 2] = make_float2(p2, p3);
        *(float2*)&out[(long)w * 2]      = make_float2(p4 + sb[0], p5 + sb[1]);
    }
}

// ================= ev-gather + global min (R16-champion) + PDL ==============
__global__ void gatherev_min_kernel(const float* __restrict__ ev,
                                    float* __restrict__ out, int N)
{
    pdl_trigger();
    int n = blockIdx.x * blockDim.x + threadIdx.x;
    int beg = 0, end = 0;
    if (n < N) { beg = g_off[n]; end = g_off[n + 1]; }
    pdl_wait();

    float m = 3.402823466e+38f;
    if (n < N) {
        float2 a0 = *(float2*)&out[n * 2];
        float2 a1 = make_float2(0.f, 0.f), a2 = a1, a3 = a1;
        int e = beg;
        for (; e + 4 <= end; e += 4) {
            unsigned p0 = g_elist[e],     p1 = g_elist[e + 1];
            unsigned p2 = g_elist[e + 2], p3 = g_elist[e + 3];
            float2 v0 = *(const float2*)&ev[(long)((p0 >> 16) * N + (p0 & 0xFFFFu)) * 2];
            float2 v1 = *(const float2*)&ev[(long)((p1 >> 16) * N + (p1 & 0xFFFFu)) * 2];
            float2 v2 = *(const float2*)&ev[(long)((p2 >> 16) * N + (p2 & 0xFFFFu)) * 2];
            float2 v3 = *(const float2*)&ev[(long)((p3 >> 16) * N + (p3 & 0xFFFFu)) * 2];
            a0.x += v0.x; a0.y += v0.y;
            a1.x += v1.x; a1.y += v1.y;
            a2.x += v2.x; a2.y += v2.y;
            a3.x += v3.x; a3.y += v3.y;
        }
        for (; e < end; e++) {
            unsigned p = g_elist[e];
            float2 v = *(const float2*)&ev[(long)((p >> 16) * N + (p & 0xFFFFu)) * 2];
            a0.x += v.x; a0.y += v.y;
        }
        a0.x += a1.x + a2.x + a3.x;
        a0.y += a1.y + a2.y + a3.y;
        *(float2*)&out[n * 2] = a0;
        m = fminf(a0.x, a0.y);
    }
    #pragma unroll
    for (int o = 16; o; o >>= 1)
        m = fminf(m, __shfl_xor_sync(0xffffffffu, m, o));
    __shared__ float sm[8];
    if ((threadIdx.x & 31) == 0) sm[threadIdx.x >> 5] = m;
    __syncthreads();
    if (threadIdx.x < 8) {
        m = sm[threadIdx.x];
        #pragma unroll
        for (int o = 4; o; o >>= 1)
            m = fminf(m, __shfl_xor_sync(0xffu, m, o));
        if (threadIdx.x == 0) atomicMin(&g_min_key, fenc(m));
    }
}

__global__ void mask_kernel(float* __restrict__ out,
                            const int* __restrict__ cs,
                            const int* __restrict__ ms, int N)
{
    pdl_wait();
    int n = blockIdx.x * blockDim.x + threadIdx.x;
    if (n >= N) return;
    float mn = fdec(g_min_key) - 1.0f;
    float2 v = *(float2*)&out[n * 2];
    if (cs[n] >= ms[n] - 1) v.x = mn;
    if (cs[n] == 0)         v.y = mn;
    *(float2*)&out[n * 2] = v;
}

// ================= launch =================
extern "C" void kernel_launch(void* const* d_in, const int* in_sizes, int n_in,
                              void* d_out, int out_size)
{
    const float* x  = (const float*)d_in[0];
    const int* src  = (const int*)d_in[1];
    const int* dst  = (const int*)d_in[2];
    const int* et   = (const int*)d_in[3];
    const int* cs   = (const int*)d_in[4];
    const int* ms   = (const int*)d_in[5];
    const float* W1 = (const float*)d_in[6];
    const float* L1 = (const float*)d_in[7];
    const float* b1 = (const float*)d_in[8];
    const float* W2 = (const float*)d_in[9];
    const float* L2 = (const float*)d_in[10];
    const float* b2 = (const float*)d_in[11];
    const float* W3 = (const float*)d_in[12];
    const float* L3 = (const float*)d_in[13];
    const float* b3 = (const float*)d_in[14];

    const int N = in_sizes[0] / 128;
    const int E = in_sizes[1];
    float* out = (float*)d_out;

    __half* tx;
    float *bufA, *bufB, *ev;
    __nv_bfloat16 *w1h, *w1l, *w2h, *w2l;
    cudaGetSymbolAddress((void**)&tx,   g_tx);
    cudaGetSymbolAddress((void**)&bufA, g_bufA);
    cudaGetSymbolAddress((void**)&bufB, g_bufB);
    cudaGetSymbolAddress((void**)&ev,   g_ev);
    cudaGetSymbolAddress((void**)&w1h,  g_w1h);
    cudaGetSymbolAddress((void**)&w1l,  g_w1l);
    cudaGetSymbolAddress((void**)&w2h,  g_w2h);
    cudaGetSymbolAddress((void**)&w2l,  g_w2l);

    // smem: A(hi/lo)[128][K+8] + ONE weight (hi/lo)[K][72], bf16
    constexpr int SMEM1 = (2 * 128 * (128 + 8) + 2 * 128 * 72) * 2;  // 106496
    constexpr int SMEM2 = (2 * 128 * (64 + 8)  + 2 * 64  * 72) * 2;  // 55296
    cudaFuncSetAttribute(gemm_tc3_kernel<128, false>,
                         cudaFuncAttributeMaxDynamicSharedMemorySize, SMEM1);
    cudaFuncSetAttribute(gemm_tc3_kernel<64, true>,
                         cudaFuncAttributeMaxDynamicSharedMemorySize, SMEM2);

    static cudaStream_t s2 = nullptr;
    static cudaEvent_t evFork = nullptr, evCSR = nullptr;
    if (!s2) {
        cudaStreamCreateWithFlags(&s2, cudaStreamNonBlocking);
        cudaEventCreateWithFlags(&evFork, cudaEventDisableTiming);
        cudaEventCreateWithFlags(&evCSR,  cudaEventDisableTiming);
    }

    const int numTiles = (N + 127) / 128;
    int nodeBlocks = (N + 255) / 256;
    int edgeBlocks = (E + 255) / 256;
    int gatherBlocks = (N * 32 + 255) / 256;
    int scanBlocks = (N + 1023) / 1024;

    cudaLaunchAttribute pdlAttr;
    pdlAttr.id = cudaLaunchAttributeProgrammaticStreamSerialization;
    pdlAttr.val.programmaticStreamSerializationAllowed = 1;
    auto mkcfg = [&](dim3 g, int b, size_t smem) {
        cudaLaunchConfig_t c{};
        c.gridDim = g; c.blockDim = dim3(b);
        c.dynamicSmemBytes = smem; c.stream = 0;
        c.attrs = &pdlAttr; c.numAttrs = 1;
        return c;
    };

    // fork CSR branch immediately
    cudaEventRecord(evFork, 0);
    cudaStreamWaitEvent(s2, evFork, 0);

    // --- branch A (s2): CSR build (rank-based, atomic-free fill) ---
    setupB_kernel<<<nodeBlocks, 256, 0, s2>>>(N);
    hist_kernel<<<edgeBlocks, 256, 0, s2>>>(dst, E);
    scan_kernel<<<scanBlocks, 1024, 0, s2>>>(N, E);
    fill_kernel<<<edgeBlocks, 256, 0, s2>>>(src, dst, et, E);
    cudaEventRecord(evCSR, s2);

    // --- branch B (main): presplit + layer-1 GEMM (split over 3 matrices) ---
    setupA_kernel<<<(36864 + 255) / 256, 256>>>(W1, L1, W2, L2);
    gemm_tc3_kernel<128, false><<<dim3(numTiles, 3), 512, SMEM1>>>(x, N,
        w1h, w1l, b1, tx, tx + (long)N * 64, bufA);

    // --- join + PDL chain ---
    cudaStreamWaitEvent(0, evCSR, 0);
    {
        cudaLaunchConfig_t c = mkcfg(dim3(gatherBlocks), 256, 0);
        cudaLaunchKernelEx(&c, gather64_kernel<false>,
            (const __half*)tx, bufA, N,
            (const float*)nullptr, (const float*)nullptr, (const float*)nullptr,
            (float*)nullptr, (float*)nullptr);
    }
    {
        cudaLaunchConfig_t c = mkcfg(dim3(numTiles, 3), 512, SMEM2);
        cudaLaunchKernelEx(&c, gemm_tc3_kernel<64, true>,
            (const float*)bufA, N,
            (const __nv_bfloat16*)w2h, (const __nv_bfloat16*)w2l, b2,
            tx, tx + (long)N * 64, bufB);
    }
    {
        cudaLaunchConfig_t c = mkcfg(dim3(gatherBlocks), 256, 0);
        cudaLaunchKernelEx(&c, gather64_kernel<true>,
            (const __half*)tx, bufB, N, W3, L3, b3, ev, out);
    }
    {
        cudaLaunchConfig_t c = mkcfg(dim3(nodeBlocks), 256, 0);
        cudaLaunchKernelEx(&c, gatherev_min_kernel, (const float*)ev, out, N);
    }
    {
        cudaLaunchConfig_t c = mkcfg(dim3(nodeBlocks), 256, 0);
        cudaLaunchKernelEx(&c, mask_kernel, out, cs, ms, N);
    }
}